// round 14
// baseline (speedup 1.0000x reference)
#include <cuda_runtime.h>
#include <cuda_bf16.h>
#include <math.h>
#include <stdint.h>

#define Bn 8192
#define Dn 1024
#define En 16
#define Hn 1024

// ---------- arch-feature gate for tcgen05 (compiles away on base sm_103) ----
#if defined(__CUDA_ARCH__) && (defined(__CUDA_ARCH_FEAT_SM103_ALL) || defined(__CUDA_ARCH_FEAT_SM100_ALL) || defined(__CUDA_ARCH_FAMILY_SPECIFIC__))
#define HAS_TC 1
#else
#define HAS_TC 0
#endif

// ---------------- scratch ---------------------------------------------------
__device__ float g_gates[Bn * En];
__device__ float g_importance[En];
__device__ float g_load[En];
__device__ int   g_tc;
__device__ float g_WT[32 * 1024];   // rows 0-15: wg^T, rows 16-31: wn^T

// B operand: tf32, tiled [4 nt][513 ch][32KB]; chunk = 256 rows x 128B SW128
#define TC_NCH 513
#define TC_BCH 32768
__device__ __align__(1024) unsigned char g_Bt[(size_t)4 * TC_NCH * TC_BCH];

#define SWZ(b) ((b) ^ (((b) >> 3) & 0x70))

// ---------------- PTX helpers ------------------------------------------------
__device__ __forceinline__ uint32_t smem_u32(const void* p) {
    uint32_t a;
    asm("{ .reg .u64 t; cvta.to.shared.u64 t, %1; cvt.u32.u64 %0, t; }" : "=r"(a) : "l"(p));
    return a;
}
__device__ __forceinline__ uint32_t ctarank() {
    uint32_t r; asm("mov.u32 %0, %%cluster_ctarank;" : "=r"(r)); return r;
}
#define MBAR_INIT(a, c) asm volatile("mbarrier.init.shared.b64 [%0], %1;" :: "r"(a), "r"((uint32_t)(c)) : "memory")
#define MBAR_EXPECT_TX(a, n) asm volatile("mbarrier.arrive.expect_tx.shared.b64 _, [%0], %1;" :: "r"(a), "r"((uint32_t)(n)) : "memory")
#define MBAR_ARRIVE(a) asm volatile("mbarrier.arrive.shared.b64 _, [%0];" :: "r"(a) : "memory")
#define MBAR_WAIT(a, ph) do {                                                   \
    uint32_t _m = (a), _p = (ph), _d;                                           \
    asm volatile("{ .reg .pred p; mbarrier.try_wait.parity.acquire.cta.shared::cta.b64 p, [%1], %2; selp.b32 %0,1,0,p; }" \
        : "=r"(_d) : "r"(_m), "r"(_p) : "memory");                              \
    if (!_d) {                                                                  \
        asm volatile("{ .reg .pred P1; W%=: mbarrier.try_wait.parity.acquire.cta.shared::cta.b64 P1, [%0], %1, 0x989680; @P1 bra.uni D%=; bra.uni W%=; D%=: }" \
            :: "r"(_m), "r"(_p) : "memory");                                    \
    }                                                                           \
} while (0)
#define MBAR_WAIT_RLX(a, ph) do {                                               \
    uint32_t _m = (a), _p = (ph), _d;                                           \
    asm volatile("{ .reg .pred p; mbarrier.try_wait.parity.relaxed.cta.shared::cta.b64 p, [%1], %2, 0x989680; selp.b32 %0,1,0,p; }" \
        : "=r"(_d) : "r"(_m), "r"(_p) : "memory");                              \
    if (!_d) {                                                                  \
        asm volatile("{ .reg .pred P1; W%=: mbarrier.try_wait.parity.relaxed.cta.shared::cta.b64 P1, [%0], %1, 0x989680; @P1 bra.uni D%=; bra.uni W%=; D%=: }" \
            :: "r"(_m), "r"(_p) : "memory");                                    \
    }                                                                           \
} while (0)
#define CLUSTER_SYNC() do {                                                     \
    asm volatile("barrier.cluster.arrive.aligned;" ::: "memory");               \
    asm volatile("barrier.cluster.wait.aligned;" ::: "memory");                 \
} while (0)

__device__ __forceinline__ void bulk_g2s_mc(uint32_t dst, const void* src, uint32_t bytes,
                                            uint32_t mbar, uint16_t mask) {
    asm volatile("cp.async.bulk.shared::cluster.global.mbarrier::complete_tx::bytes.multicast::cluster "
        "[%0], [%1], %2, [%3], %4;"
        :: "r"(dst), "l"(src), "r"(bytes), "r"(mbar), "h"(mask) : "memory");
}
__device__ __forceinline__ void cpa16(uint32_t d, const void* s) {
    asm volatile("cp.async.cg.shared.global [%0], [%1], 16;" :: "r"(d), "l"(s) : "memory");
}
#define CPA_COMMIT() asm volatile("cp.async.commit_group;" ::: "memory")
#define CPA_WAIT2()  asm volatile("cp.async.wait_group 2;" ::: "memory")

__device__ __forceinline__ uint32_t f2tf(float v) {
    uint32_t r; asm("cvt.rna.tf32.f32 %0, %1;" : "=r"(r) : "f"(v)); return r;
}
__device__ __forceinline__ void mma_tf32(float* c, uint32_t a0, uint32_t a1, uint32_t a2, uint32_t a3,
                                         uint32_t b0, uint32_t b1) {
    asm volatile("mma.sync.aligned.m16n8k8.row.col.f32.tf32.tf32.f32 "
        "{%0,%1,%2,%3},{%4,%5,%6,%7},{%8,%9},{%0,%1,%2,%3};"
        : "+f"(c[0]), "+f"(c[1]), "+f"(c[2]), "+f"(c[3])
        : "r"(a0), "r"(a1), "r"(a2), "r"(a3), "r"(b0), "r"(b1));
}

// ---------------- kernel 0: init ---------------------------------------------
__global__ void k_init() {
    int t = threadIdx.x;
    if (t < En) { g_importance[t] = 0.f; g_load[t] = 0.f; }
    if (t == 0) g_tc = HAS_TC;
}

// ---------------- kernel 0b: transpose gate weights --------------------------
__global__ __launch_bounds__(256) void k_prep_w(
    const float* __restrict__ wg, const float* __restrict__ wn)
{
    int row = blockIdx.x;
    const float* src = (row < 16) ? wg : wn;
    int e = row & 15;
    for (int d = threadIdx.x; d < Dn; d += 256)
        g_WT[row * 1024 + d] = src[d * En + e];
}

// ---------------- kernel 1: fused logits + softmax + top-9 + gates + load ----
__global__ __launch_bounds__(512, 3) void k_logits_gate(
    const float* __restrict__ x, const float* __restrict__ noise)
{
    __shared__ float xs[4][1024];
    __shared__ float part_c[4][16];
    __shared__ float part_n[4][16];
    __shared__ float s_nz[4][16], s_cl[4][16], s_sd[4][16];
    __shared__ float s_g[4][16],  s_ld[4][16];
    int tid = threadIdx.x;
    int b0 = blockIdx.x * 4;

    ((float4*)xs)[tid*2]   = ((const float4*)(x + (size_t)b0 * Dn))[tid*2];
    ((float4*)xs)[tid*2+1] = ((const float4*)(x + (size_t)b0 * Dn))[tid*2+1];
    __syncthreads();

    int w = tid >> 5, lane = tid & 31;
    const float4* Wg4 = (const float4*)(g_WT + w * 1024);
    const float4* Wn4 = (const float4*)(g_WT + (16 + w) * 1024);

    float sc[4] = {0.f,0.f,0.f,0.f};
    float sn[4] = {0.f,0.f,0.f,0.f};
    #pragma unroll
    for (int it = 0; it < 8; it++) {
        int q = it * 32 + lane;
        float4 wgv = Wg4[q];
        float4 wnv = Wn4[q];
        #pragma unroll
        for (int r = 0; r < 4; r++) {
            float4 xv = *(const float4*)&xs[r][q * 4];
            float dc = fmaf(xv.x, wgv.x, fmaf(xv.y, wgv.y, fmaf(xv.z, wgv.z, xv.w * wgv.w)));
            float dn = fmaf(xv.x, wnv.x, fmaf(xv.y, wnv.y, fmaf(xv.z, wnv.z, xv.w * wnv.w)));
            sc[r] += dc;
            sn[r] += dn;
        }
    }
    #pragma unroll
    for (int r = 0; r < 4; r++) {
        float vc = sc[r], vn = sn[r];
        #pragma unroll
        for (int off = 16; off; off >>= 1) {
            vc += __shfl_down_sync(0xffffffffu, vc, off);
            vn += __shfl_down_sync(0xffffffffu, vn, off);
        }
        if (lane == 0) { part_c[r][w] = vc; part_n[r][w] = vn; }
    }
    __syncthreads();

    if (tid < 64) {
        int r = tid >> 4, e2 = tid & 15;
        int b = b0 + r;
        float clean = part_c[r][e2];
        float raw   = part_n[r][e2];
        float sp = fmaxf(raw, 0.f) + log1pf(expf(-fabsf(raw)));
        float sd = sp + 0.01f;
        float nz = clean + noise[b * En + e2] * sd;
        s_cl[r][e2] = clean;
        s_sd[r][e2] = sd;
        s_nz[r][e2] = nz;
    }
    __syncthreads();

    if (tid < 4) {
        int r = tid, b = b0 + r;
        float nz[16], cl[16], sd[16];
        #pragma unroll
        for (int e = 0; e < 16; e++) { nz[e] = s_nz[r][e]; cl[e] = s_cl[r][e]; sd[e] = s_sd[r][e]; }

        float m = nz[0];
        #pragma unroll
        for (int e = 1; e < 16; e++) m = fmaxf(m, nz[e]);
        float p[16], sum = 0.f;
        #pragma unroll
        for (int e = 0; e < 16; e++) { p[e] = expf(nz[e] - m); sum += p[e]; }
        float inv = 1.f / sum;
        #pragma unroll
        for (int e = 0; e < 16; e++) p[e] *= inv;

        float topv[9]; int topi[9]; unsigned mask = 0;
        #pragma unroll
        for (int t = 0; t < 9; t++) {
            float best = -1.f; int bi = 0;
            #pragma unroll
            for (int e = 0; e < 16; e++) {
                bool ok = (!((mask >> e) & 1u)) && (p[e] > best);
                if (ok) { best = p[e]; bi = e; }
            }
            topv[t] = best; topi[t] = bi; mask |= (1u << bi);
        }

        float ksum = 0.f;
        #pragma unroll
        for (int t = 0; t < 8; t++) ksum += topv[t];
        float dinv = 1.f / (ksum + 1e-6f);

        float g16[16];
        #pragma unroll
        for (int e = 0; e < 16; e++) {
            float ge = 0.f;
            #pragma unroll
            for (int t = 0; t < 8; t++) ge = (topi[t] == e) ? topv[t] * dinv : ge;
            g16[e] = ge;
            s_g[r][e] = ge;
        }
        #pragma unroll
        for (int i = 0; i < 4; i++)
            ((float4*)(g_gates + (size_t)b * 16))[i] =
                make_float4(g16[4*i], g16[4*i+1], g16[4*i+2], g16[4*i+3]);

        float thr_in = topv[8], thr_out = topv[7];
        #pragma unroll
        for (int e = 0; e < 16; e++) {
            bool in = nz[e] > thr_in;
            float thr = in ? thr_in : thr_out;
            float z = (cl[e] - thr) / sd[e];
            s_ld[r][e] = 0.5f * (1.f + erff(z * 0.70710678118654752440f));
        }
    }
    __syncthreads();

    if (tid < 16) {
        float si = 0.f, sl = 0.f;
        #pragma unroll
        for (int r = 0; r < 4; r++) { si += s_g[r][tid]; sl += s_ld[r][tid]; }
        atomicAdd(&g_importance[tid], si);
        atomicAdd(&g_load[tid], sl);
    }
}

// ---------------- kernel 3: loss (off GEMM critical path) --------------------
__global__ void k_loss(float* __restrict__ out)
{
    if (threadIdx.x == 0 && blockIdx.x == 0) {
        float mi = 0.f, ml = 0.f;
        for (int e = 0; e < En; e++) { mi += g_importance[e]; ml += g_load[e]; }
        mi *= (1.f / En); ml *= (1.f / En);
        float vi = 0.f, vl = 0.f;
        for (int e = 0; e < En; e++) {
            float d1 = g_importance[e] - mi; vi += d1 * d1;
            float d2 = g_load[e] - ml;       vl += d2 * d2;
        }
        vi /= (En - 1); vl /= (En - 1);
        out[(size_t)Bn * Hn] = 0.01f * (vi / (mi * mi + 1e-10f) + vl / (ml * ml + 1e-10f));
    }
}

// ---------------- kernel 5: B = expert_w -> tf32, 32KB chunks, swizzled ------
__global__ __launch_bounds__(256) void k_prep_b(const float* __restrict__ ew)
{
#if HAS_TC
    int h64 = blockIdx.x;
    int kc  = blockIdx.y;
    __shared__ float ts[64][65];
    int tid = threadIdx.x;
    int kl = tid >> 4;
    int h4 = (tid & 15) * 4;
    #pragma unroll
    for (int r = 0; r < 4; r++) {
        int kk = kl + r * 16;
        float4 v = *(const float4*)(ew + (size_t)(kc * 64 + kk) * Hn + h64 * 64 + h4);
        ts[h4 + 0][kk] = v.x; ts[h4 + 1][kk] = v.y;
        ts[h4 + 2][kk] = v.z; ts[h4 + 3][kk] = v.w;
    }
    __syncthreads();
    #pragma unroll
    for (int r2 = 0; r2 < 2; r2++) {
        int it = tid + r2 * 256;
        int hl = it >> 3, kg = it & 7;
        uint32_t w[8];
        #pragma unroll
        for (int j = 0; j < 8; j++) w[j] = f2tf(ts[hl][kg * 8 + j]);
        int hg = h64 * 64 + hl;
        int ht = hg >> 8, rr = hg & 255;
        int ch32 = kc * 2 + (kg >> 2);
        uint32_t bytec = (uint32_t)((kg & 3) * 32);
        size_t base = ((size_t)(ht * TC_NCH + ch32)) * TC_BCH;
        *(uint4*)(g_Bt + base + SWZ((uint32_t)(rr * 128) + bytec))      = make_uint4(w[0], w[1], w[2], w[3]);
        *(uint4*)(g_Bt + base + SWZ((uint32_t)(rr * 128) + bytec + 16)) = make_uint4(w[4], w[5], w[6], w[7]);
    }
#endif
}

__global__ __launch_bounds__(256) void k_prep_bb(const float* __restrict__ eb)
{
#if HAS_TC
    int ht = blockIdx.x;
    int row = threadIdx.x;
    int hg = ht * 256 + row;
    #pragma unroll
    for (int kg = 0; kg < 4; kg++) {
        uint32_t w[8];
        #pragma unroll
        for (int j = 0; j < 8; j++) {
            int c = kg * 8 + j;
            w[j] = (c < 16) ? f2tf(eb[c * Hn + hg]) : 0u;
        }
        size_t base = ((size_t)(ht * TC_NCH + 512)) * TC_BCH;
        uint32_t bytec = (uint32_t)(kg * 32);
        *(uint4*)(g_Bt + base + SWZ((uint32_t)(row * 128) + bytec))      = make_uint4(w[0], w[1], w[2], w[3]);
        *(uint4*)(g_Bt + base + SWZ((uint32_t)(row * 128) + bytec + 16)) = make_uint4(w[4], w[5], w[6], w[7]);
    }
#endif
}

// =============================================================================
//  kernel 7 (tc path): fused tf32 GEMM, KC=32, 4-stage, 2-CTA B mcast
//  576 threads. SINGLE full-barrier per stage: count 17 (16 converter warps +
//  producer arrive.expect_tx) + 32KB tx; issuer does ONE wait per chunk.
// =============================================================================
#define TC_MT 128
#define TC_NT 256
#define CSZ 2
#define CMASK ((uint16_t)0x3)
#define NST 4
#define SM_A(s)   (1024u + (uint32_t)(s) * 16384u)     // 1024..66560
#define SM_B(s)   (66560u + (uint32_t)(s) * 32768u)    // 66560..197632
#define SM_GS     197632u
#define GEMM2_SMEM 206848

__global__ __launch_bounds__(576, 1) __cluster_dims__(1, CSZ, 1)
void k_gemm_tc2(const float* __restrict__ x, float* __restrict__ out)
{
#if HAS_TC
    extern __shared__ unsigned char smc[];
    const uint32_t sb = smem_u32(smc);
    const uint32_t mb_f  = sb + 0;      // fused full barriers [4]
    const uint32_t mb_dn = sb + 64;     // done barriers [4]
    const uint32_t mb_done = sb + 96;
    const uint32_t tptr    = sb + 128;
    float* gs = (float*)(smc + SM_GS);

    const int tid = threadIdx.x, wid = tid >> 5, lane = tid & 31;
    const int nt = blockIdx.x, mt = blockIdx.y;
    const int bM = mt * TC_MT;
    const uint32_t rank = ctarank();

    if (tid == 0) {
        #pragma unroll
        for (int s = 0; s < NST; s++) {
            MBAR_INIT(mb_f + s * 8, 17);     // 16 converter warps + producer expect_tx
            MBAR_INIT(mb_dn + s * 8, CSZ);
        }
        MBAR_INIT(mb_done, CSZ);
    }
    for (int i = tid; i < TC_MT * En; i += 576) {
        int r = i >> 4, e = i & 15;
        gs[r * 17 + e] = g_gates[(size_t)(bM + r) * En + e];
    }
    __syncthreads();
    if (wid == 17) {
        asm volatile("tcgen05.alloc.cta_group::1.sync.aligned.shared::cta.b32 [%0], %1;" :: "r"(tptr), "r"((uint32_t)TC_NT) : "memory");
        asm volatile("tcgen05.relinquish_alloc_permit.cta_group::1.sync.aligned;");
    }
    __syncthreads();
    CLUSTER_SYNC();
    uint32_t tmem;
    asm volatile("ld.shared.b32 %0, [%1];" : "=r"(tmem) : "r"(tptr));

    const uint64_t DESC_BASE =
        (uint64_t(2) << 61) | (uint64_t(1) << 46) | (uint64_t(64) << 32) | (uint64_t(1) << 16);
    const uint32_t GIDESC = (1u<<4) | (2u<<7) | (2u<<10) | ((TC_NT/8u)<<17) | ((TC_MT/16u)<<24);

    if (tid < 512) {
        // ---- A converters: 8 values/thread/chunk, convert-before-wait ------
        const int r  = tid >> 2;            // row 0..127
        const int q4 = tid & 3;             // 8-col group within 32-col chunk
        const float* xp = x + (size_t)(bM + r) * Dn + (size_t)q4 * 8;
        const uint32_t rowb = (uint32_t)(r * 128 + q4 * 32);
        const uint32_t off0 = SWZ(rowb);
        const uint32_t off1 = SWZ(rowb + 16);
        const float* grow = gs + r * 17;
        uint32_t dph[NST] = {0, 0, 0, 0};
        int i = 0;
        for (int db = 0; db < 32; db++) {   // 32-col x blocks
            float xr[8];
            {
                const float4* xv = (const float4*)(xp + db * 32);
                float4 f0 = xv[0], f1 = xv[1];
                xr[0] = f0.x; xr[1] = f0.y; xr[2] = f0.z; xr[3] = f0.w;
                xr[4] = f1.x; xr[5] = f1.y; xr[6] = f1.z; xr[7] = f1.w;
            }
            for (int e = 0; e < 16; e++, i++) {
                int s = i & (NST - 1);
                float g = grow[e];
                uint32_t w[8];
                #pragma unroll
                for (int j = 0; j < 8; j++) w[j] = f2tf(g * xr[j]);
                if (i >= NST) { MBAR_WAIT(mb_dn + s * 8, dph[s]); dph[s] ^= 1; }
                unsigned char* ap = smc + SM_A(s);
                *(uint4*)(ap + off0) = make_uint4(w[0], w[1], w[2], w[3]);
                *(uint4*)(ap + off1) = make_uint4(w[4], w[5], w[6], w[7]);
                asm volatile("fence.proxy.async.shared::cta;" ::: "memory");
                __syncwarp();
                if (lane == 0) MBAR_ARRIVE(mb_f + s * 8);
            }
        }
        // bias chunk (i == 512): global cols 0..15 = gates, 16..31 = 0
        {
            int s = 0;
            uint32_t w[8];
            #pragma unroll
            for (int j = 0; j < 8; j++) {
                int c = q4 * 8 + j;
                w[j] = (c < 16) ? f2tf(grow[c]) : 0u;
            }
            MBAR_WAIT(mb_dn + s * 8, dph[s]); dph[s] ^= 1;
            unsigned char* ap = smc + SM_A(s);
            *(uint4*)(ap + off0) = make_uint4(w[0], w[1], w[2], w[3]);
            *(uint4*)(ap + off1) = make_uint4(w[4], w[5], w[6], w[7]);
            asm volatile("fence.proxy.async.shared::cta;" ::: "memory");
            __syncwarp();
            if (lane == 0) MBAR_ARRIVE(mb_f + s * 8);
        }
    } else if (tid == 512) {
        // ---- B producer: 2-way multicast cooperative halves ----------------
        const unsigned char* pBt = g_Bt + (size_t)nt * TC_NCH * TC_BCH;
        const uint32_t hoff = rank * 16384u;
        uint32_t dph[NST] = {0, 0, 0, 0};
        for (int i = 0; i <= 512; i++) {
            int s = i & (NST - 1);
            if (i >= NST) { MBAR_WAIT_RLX(mb_dn + s * 8, dph[s]); dph[s] ^= 1; }
            int cB = (i < 512) ? ((i & 15) * 32 + (i >> 4)) : 512;
            uint32_t mbf = mb_f + s * 8;
            MBAR_EXPECT_TX(mbf, TC_BCH);    // arrival #17 + 32KB tx
            bulk_g2s_mc(sb + SM_B(s) + hoff, pBt + (size_t)cB * TC_BCH + hoff, 16384u, mbf, CMASK);
        }
    } else if (tid == 544) {
        // ---- MMA issuer: single wait per chunk ------------------------------
        uint32_t fph[NST] = {0, 0, 0, 0};
        uint32_t acc = 0;
        for (int i = 0; i <= 512; i++) {
            int s = i & (NST - 1);
            MBAR_WAIT(mb_f + s * 8, fph[s]); fph[s] ^= 1;
            uint64_t da = DESC_BASE | ((uint64_t)((sb + SM_A(s)) >> 4) & 0x3FFF);
            uint64_t db = DESC_BASE | ((uint64_t)((sb + SM_B(s)) >> 4) & 0x3FFF);
            #pragma unroll
            for (int ks = 0; ks < 4; ks++) {
                asm volatile("{ .reg .pred p; setp.ne.u32 p, %5, 0;\n"
                    "tcgen05.mma.cta_group::1.kind::tf32 [%0], %1, %2, %3, {%4,%4,%4,%4}, p; }"
                    :: "r"(tmem), "l"(da + ks * 2), "l"(db + ks * 2), "r"(GIDESC), "r"(0u), "r"(acc) : "memory");
                acc = 1;
            }
            uint32_t mtarget = (i == 512) ? mb_done : (mb_dn + s * 8);
            asm volatile(
                "tcgen05.commit.cta_group::1.mbarrier::arrive::one.shared::cluster.multicast::cluster.b64 [%0], %1;"
                :: "r"(mtarget), "h"(CMASK) : "memory");
        }
    }

    // ---------------- epilogue -----------------------------------------------
    MBAR_WAIT(mb_done, 0);
    asm volatile("tcgen05.fence::after_thread_sync;" ::: "memory");

    if (wid < 4) {
        int row = bM + wid * 32 + lane;
        float* orow = out + (size_t)row * Hn + nt * TC_NT;
        #pragma unroll
        for (int cc = 0; cc < 8; cc++) {
            uint32_t r[32];
            asm volatile(
                "tcgen05.ld.sync.aligned.32x32b.x32.b32 "
                "{%0,%1,%2,%3,%4,%5,%6,%7,%8,%9,%10,%11,%12,%13,%14,%15,"
                "%16,%17,%18,%19,%20,%21,%22,%23,%24,%25,%26,%27,%28,%29,%30,%31}, [%32];"
                : "=r"(r[0]),"=r"(r[1]),"=r"(r[2]),"=r"(r[3]),"=r"(r[4]),"=r"(r[5]),"=r"(r[6]),"=r"(r[7]),
                  "=r"(r[8]),"=r"(r[9]),"=r"(r[10]),"=r"(r[11]),"=r"(r[12]),"=r"(r[13]),"=r"(r[14]),"=r"(r[15]),
                  "=r"(r[16]),"=r"(r[17]),"=r"(r[18]),"=r"(r[19]),"=r"(r[20]),"=r"(r[21]),"=r"(r[22]),"=r"(r[23]),
                  "=r"(r[24]),"=r"(r[25]),"=r"(r[26]),"=r"(r[27]),"=r"(r[28]),"=r"(r[29]),"=r"(r[30]),"=r"(r[31])
                : "r"(tmem + cc * 32));
            asm volatile("tcgen05.wait::ld.sync.aligned;" ::: "memory");
            #pragma unroll
            for (int q = 0; q < 8; q++) {
                *(float4*)(orow + cc * 32 + q * 4) = make_float4(
                    __uint_as_float(r[q*4+0]), __uint_as_float(r[q*4+1]),
                    __uint_as_float(r[q*4+2]), __uint_as_float(r[q*4+3]));
            }
        }
    }
    __syncthreads();
    if (wid == 17)
        asm volatile("tcgen05.dealloc.cta_group::1.sync.aligned.b32 %0, %1;" :: "r"(tmem), "r"((uint32_t)TC_NT));
    CLUSTER_SYNC();
#endif
}

// =============================================================================
//  PATH B: tf32 mma.sync GEMM fallback (base-target legal)
// =============================================================================
#define BM 128
#define BN 128
#define BK 32
#define STAGES 4
#define ASTR 44
#define BSTR 136
#define GSTR 17
#define A_ST_FLT (BM * ASTR)
#define B_ST_FLT (BK * BSTR)
#define NTILES (En * Dn / BK)

__global__ __launch_bounds__(256, 1) void k_gemm_mma(
    const float* __restrict__ x, const float* __restrict__ ew,
    const float* __restrict__ eb, float* __restrict__ out)
{
    if (g_tc) return;

    extern __shared__ float sm[];
    float* As  = sm;
    float* Bs  = sm + STAGES * A_ST_FLT;
    float* gs  = Bs + STAGES * B_ST_FLT;
    float* ebs = gs + BM * GSTR;

    const int tid  = threadIdx.x;
    const int lane = tid & 31;
    const int wid  = tid >> 5;
    const int wm   = wid >> 2;
    const int wn   = wid & 3;
    const int grp  = lane >> 2;
    const int qid  = lane & 3;
    const int bM = blockIdx.y * BM;
    const int bN = blockIdx.x * BN;

    for (int i = tid; i < BM * En; i += 256) {
        int r = i >> 4, e = i & 15;
        gs[r * GSTR + e] = g_gates[(size_t)(bM + r) * En + e];
    }
    for (int i = tid; i < En * BN; i += 256) {
        int e = i >> 7, c = i & 127;
        ebs[e * BN + c] = eb[(size_t)e * Hn + bN + c];
    }

    const uint32_t sbase = smem_u32(sm);
    const int ar = tid >> 1, ac = (tid & 1) * 4;
    const int bk0 = tid >> 5, bc0 = (tid & 31) * 4;
    const uint32_t adst0 = sbase + (uint32_t)(ar * ASTR + ac) * 4u;
    const uint32_t bdst0 = sbase + (uint32_t)(STAGES * A_ST_FLT + bk0 * BSTR + bc0) * 4u;

#define LOAD_TILE(kt, s) do {                                                   \
        int _d0 = ((kt) * BK) & (Dn - 1);                                       \
        cpa16(adst0 + (uint32_t)((s) * A_ST_FLT * 4),                           \
              x + (size_t)(bM + ar) * Dn + _d0 + ac);                           \
        const float* _bw = ew + (size_t)((kt) * BK + bk0) * Hn + bN + bc0;      \
        uint32_t _bd = bdst0 + (uint32_t)((s) * B_ST_FLT * 4);                  \
        cpa16(_bd,                      _bw);                                   \
        cpa16(_bd + 8u*BSTR*4u,         _bw + (size_t)8  * Hn);                 \
        cpa16(_bd + 16u*BSTR*4u,        _bw + (size_t)16 * Hn);                 \
        cpa16(_bd + 24u*BSTR*4u,        _bw + (size_t)24 * Hn);                 \
    } while (0)

    #pragma unroll
    for (int s = 0; s < STAGES - 1; s++) { LOAD_TILE(s, s); CPA_COMMIT(); }

    float acc[4][4][4];
    #pragma unroll
    for (int mi = 0; mi < 4; mi++)
        #pragma unroll
        for (int ni = 0; ni < 4; ni++)
            #pragma unroll
            for (int q = 0; q < 4; q++) acc[mi][ni][q] = 0.f;

    const int aoff = (wm * 64 + grp) * ASTR + qid;
    const int boff = qid * BSTR + wn * 32 + grp;

    float g0[4], g1[4];
    __syncthreads();

    for (int kt = 0; kt < NTILES; kt++) {
        CPA_WAIT2();
        __syncthreads();

        if ((kt & 31) == 0) {
            int e = kt >> 5;
            #pragma unroll
            for (int mi = 0; mi < 4; mi++) {
                g0[mi] = gs[(wm * 64 + mi * 16 + grp) * GSTR + e];
                g1[mi] = gs[(wm * 64 + mi * 16 + grp + 8) * GSTR + e];
            }
        }

        int nk = kt + STAGES - 1;
        if (nk < NTILES) LOAD_TILE(nk, nk & (STAGES - 1));
        CPA_COMMIT();

        const float* Ap = As + (kt & (STAGES - 1)) * A_ST_FLT + aoff;
        const float* Bp = Bs + (kt & (STAGES - 1)) * B_ST_FLT + boff;

        #pragma unroll
        for (int ks = 0; ks < 4; ks++) {
            uint32_t bf[4][2];
            #pragma unroll
            for (int ni = 0; ni < 4; ni++) {
                bf[ni][0] = f2tf(Bp[(ks * 8) * BSTR + ni * 8]);
                bf[ni][1] = f2tf(Bp[(ks * 8 + 4) * BSTR + ni * 8]);
            }
            #pragma unroll
            for (int mi = 0; mi < 4; mi++) {
                const float* ab = Ap + mi * 16 * ASTR + ks * 8;
                uint32_t a0 = f2tf(g0[mi] * ab[0]);
                uint32_t a1 = f2tf(g1[mi] * ab[8 * ASTR]);
                uint32_t a2 = f2tf(g0[mi] * ab[4]);
                uint32_t a3 = f2tf(g1[mi] * ab[8 * ASTR + 4]);
                #pragma unroll
                for (int ni = 0; ni < 4; ni++)
                    mma_tf32(acc[mi][ni], a0, a1, a2, a3, bf[ni][0], bf[ni][1]);
            }
        }
    }

    #pragma unroll
    for (int mi = 0; mi < 4; mi++) {
        int r0 = wm * 64 + mi * 16 + grp;
        #pragma unroll
        for (int e = 0; e < En; e++) {
            float ge0 = gs[r0 * GSTR + e];
            float ge1 = gs[(r0 + 8) * GSTR + e];
            #pragma unroll
            for (int ni = 0; ni < 4; ni++) {
                int c0 = wn * 32 + ni * 8 + 2 * qid;
                float b0v = ebs[e * BN + c0];
                float b1v = ebs[e * BN + c0 + 1];
                acc[mi][ni][0] = fmaf(ge0, b0v, acc[mi][ni][0]);
                acc[mi][ni][1] = fmaf(ge0, b1v, acc[mi][ni][1]);
                acc[mi][ni][2] = fmaf(ge1, b0v, acc[mi][ni][2]);
                acc[mi][ni][3] = fmaf(ge1, b1v, acc[mi][ni][3]);
            }
        }
    }

    #pragma unroll
    for (int mi = 0; mi < 4; mi++) {
        int r0 = bM + wm * 64 + mi * 16 + grp;
        #pragma unroll
        for (int ni = 0; ni < 4; ni++) {
            int c0 = bN + wn * 32 + ni * 8 + 2 * qid;
            *(float2*)(out + (size_t)r0 * Hn + c0)       = make_float2(acc[mi][ni][0], acc[mi][ni][1]);
            *(float2*)(out + (size_t)(r0 + 8) * Hn + c0) = make_float2(acc[mi][ni][2], acc[mi][ni][3]);
        }
    }
#undef LOAD_TILE
}

// ---------------- launch ------------------------------------------------------
extern "C" void kernel_launch(void* const* d_in, const int* in_sizes, int n_in,
                              void* d_out, int out_size)
{
    const float* x     = (const float*)d_in[0];
    const float* wg    = (const float*)d_in[1];
    const float* wn    = (const float*)d_in[2];
    const float* ew    = (const float*)d_in[3];
    const float* eb    = (const float*)d_in[4];
    const float* noise = (const float*)d_in[5];
    float* out = (float*)d_out;

    static const int MMA_SMEM = (STAGES * (A_ST_FLT + B_ST_FLT) + BM * GSTR + En * BN) * 4;
    static cudaStream_t s2 = nullptr, s3 = nullptr;
    static cudaEvent_t ev_fork = nullptr, ev_join = nullptr, ev_gate = nullptr, ev_loss = nullptr;
    if (!s2) {
        cudaStreamCreateWithFlags(&s2, cudaStreamNonBlocking);
        cudaStreamCreateWithFlags(&s3, cudaStreamNonBlocking);
        cudaEventCreateWithFlags(&ev_fork, cudaEventDisableTiming);
        cudaEventCreateWithFlags(&ev_join, cudaEventDisableTiming);
        cudaEventCreateWithFlags(&ev_gate, cudaEventDisableTiming);
        cudaEventCreateWithFlags(&ev_loss, cudaEventDisableTiming);
        cudaFuncSetAttribute(k_gemm_tc2, cudaFuncAttributeMaxDynamicSharedMemorySize, GEMM2_SMEM);
        cudaFuncSetAttribute(k_gemm_mma, cudaFuncAttributeMaxDynamicSharedMemorySize, MMA_SMEM);
    }

    k_init<<<1, 32>>>();
    k_prep_w<<<32, 256>>>(wg, wn);

    // fork: B preprocessing runs concurrently with the gating chain
    cudaEventRecord(ev_fork, 0);
    cudaStreamWaitEvent(s2, ev_fork, 0);
    k_prep_b<<<dim3(16, 256), 256, 0, s2>>>(ew);
    k_prep_bb<<<4, 256, 0, s2>>>(eb);
    cudaEventRecord(ev_join, s2);

    // gating (produces g_gates + importance/load accumulators)
    k_logits_gate<<<Bn / 4, 512>>>(x, noise);

    // loss on s3 (off the GEMM critical path), joined back AFTER the GEMM
    cudaEventRecord(ev_gate, 0);
    cudaStreamWaitEvent(s3, ev_gate, 0);
    k_loss<<<1, 32, 0, s3>>>(out);
    cudaEventRecord(ev_loss, s3);

    // join prep, then GEMM
    cudaStreamWaitEvent(0, ev_join, 0);
    k_gemm_tc2<<<dim3(Hn / TC_NT, Bn / TC_MT), 576, GEMM2_SMEM>>>(x, out);

    // mma.sync fallback (early-exits if tc path is live)
    k_gemm_mma<<<dim3(Hn / BN, Bn / BM), 256, MMA_SMEM>>>(x, ew, eb, out);

    // rejoin s3 so the capture graph has no unjoined work
    cudaStreamWaitEvent(0, ev_loss, 0);
}

// round 15
// speedup vs baseline: 1.0349x; 1.0349x over previous
#include <cuda_runtime.h>
#include <cuda_bf16.h>
#include <math.h>
#include <stdint.h>

#define Bn 8192
#define Dn 1024
#define En 16
#define Hn 1024

// ---------- arch-feature gate for tcgen05 (compiles away on base sm_103) ----
#if defined(__CUDA_ARCH__) && (defined(__CUDA_ARCH_FEAT_SM103_ALL) || defined(__CUDA_ARCH_FEAT_SM100_ALL) || defined(__CUDA_ARCH_FAMILY_SPECIFIC__))
#define HAS_TC 1
#else
#define HAS_TC 0
#endif

// ---------------- scratch ---------------------------------------------------
__device__ float g_clean[Bn * En];
__device__ float g_stddev[Bn * En];
__device__ float g_noisy[Bn * En];
__device__ float g_gates[Bn * En];
__device__ float g_importance[En];
__device__ float g_load[En];
__device__ int   g_tc;
__device__ float g_WT[32 * 1024];   // rows 0-15: wg^T, rows 16-31: wn^T

// B operand: tf32, tiled [4 nt][513 ch][32KB]; chunk = 256 rows x 128B SW128
#define TC_NCH 513
#define TC_BCH 32768
__device__ __align__(1024) unsigned char g_Bt[(size_t)4 * TC_NCH * TC_BCH];

#define SWZ(b) ((b) ^ (((b) >> 3) & 0x70))

// ---------------- PTX helpers ------------------------------------------------
__device__ __forceinline__ uint32_t smem_u32(const void* p) {
    uint32_t a;
    asm("{ .reg .u64 t; cvta.to.shared.u64 t, %1; cvt.u32.u64 %0, t; }" : "=r"(a) : "l"(p));
    return a;
}
__device__ __forceinline__ uint32_t ctarank() {
    uint32_t r; asm("mov.u32 %0, %%cluster_ctarank;" : "=r"(r)); return r;
}
#define MBAR_INIT(a, c) asm volatile("mbarrier.init.shared.b64 [%0], %1;" :: "r"(a), "r"((uint32_t)(c)) : "memory")
#define MBAR_EXPECT_TX(a, n) asm volatile("mbarrier.arrive.expect_tx.shared.b64 _, [%0], %1;" :: "r"(a), "r"((uint32_t)(n)) : "memory")
#define MBAR_ARRIVE(a) asm volatile("mbarrier.arrive.shared.b64 _, [%0];" :: "r"(a) : "memory")
#define MBAR_WAIT(a, ph) do {                                                   \
    uint32_t _m = (a), _p = (ph), _d;                                           \
    asm volatile("{ .reg .pred p; mbarrier.try_wait.parity.acquire.cta.shared::cta.b64 p, [%1], %2; selp.b32 %0,1,0,p; }" \
        : "=r"(_d) : "r"(_m), "r"(_p) : "memory");                              \
    if (!_d) {                                                                  \
        asm volatile("{ .reg .pred P1; W%=: mbarrier.try_wait.parity.acquire.cta.shared::cta.b64 P1, [%0], %1, 0x989680; @P1 bra.uni D%=; bra.uni W%=; D%=: }" \
            :: "r"(_m), "r"(_p) : "memory");                                    \
    }                                                                           \
} while (0)
#define MBAR_WAIT_RLX(a, ph) do {                                               \
    uint32_t _m = (a), _p = (ph), _d;                                           \
    asm volatile("{ .reg .pred p; mbarrier.try_wait.parity.relaxed.cta.shared::cta.b64 p, [%1], %2, 0x989680; selp.b32 %0,1,0,p; }" \
        : "=r"(_d) : "r"(_m), "r"(_p) : "memory");                              \
    if (!_d) {                                                                  \
        asm volatile("{ .reg .pred P1; W%=: mbarrier.try_wait.parity.relaxed.cta.shared::cta.b64 P1, [%0], %1, 0x989680; @P1 bra.uni D%=; bra.uni W%=; D%=: }" \
            :: "r"(_m), "r"(_p) : "memory");                                    \
    }                                                                           \
} while (0)
#define CLUSTER_SYNC() do {                                                     \
    asm volatile("barrier.cluster.arrive.aligned;" ::: "memory");               \
    asm volatile("barrier.cluster.wait.aligned;" ::: "memory");                 \
} while (0)

__device__ __forceinline__ void bulk_g2s_mc(uint32_t dst, const void* src, uint32_t bytes,
                                            uint32_t mbar, uint16_t mask) {
    asm volatile("cp.async.bulk.shared::cluster.global.mbarrier::complete_tx::bytes.multicast::cluster "
        "[%0], [%1], %2, [%3], %4;"
        :: "r"(dst), "l"(src), "r"(bytes), "r"(mbar), "h"(mask) : "memory");
}
__device__ __forceinline__ void cpa16(uint32_t d, const void* s) {
    asm volatile("cp.async.cg.shared.global [%0], [%1], 16;" :: "r"(d), "l"(s) : "memory");
}
#define CPA_COMMIT() asm volatile("cp.async.commit_group;" ::: "memory")
#define CPA_WAIT2()  asm volatile("cp.async.wait_group 2;" ::: "memory")

__device__ __forceinline__ uint32_t f2tf(float v) {
    uint32_t r; asm("cvt.rna.tf32.f32 %0, %1;" : "=r"(r) : "f"(v)); return r;
}
__device__ __forceinline__ void mma_tf32(float* c, uint32_t a0, uint32_t a1, uint32_t a2, uint32_t a3,
                                         uint32_t b0, uint32_t b1) {
    asm volatile("mma.sync.aligned.m16n8k8.row.col.f32.tf32.tf32.f32 "
        "{%0,%1,%2,%3},{%4,%5,%6,%7},{%8,%9},{%0,%1,%2,%3};"
        : "+f"(c[0]), "+f"(c[1]), "+f"(c[2]), "+f"(c[3])
        : "r"(a0), "r"(a1), "r"(a2), "r"(a3), "r"(b0), "r"(b1));
}

// ---------------- kernel 0: init ---------------------------------------------
__global__ void k_init() {
    int t = threadIdx.x;
    if (t < En) { g_importance[t] = 0.f; g_load[t] = 0.f; }
    if (t == 0) g_tc = HAS_TC;
}

// ---------------- kernel 0b: transpose gate weights --------------------------
__global__ __launch_bounds__(256) void k_prep_w(
    const float* __restrict__ wg, const float* __restrict__ wn)
{
    int row = blockIdx.x;
    const float* src = (row < 16) ? wg : wn;
    int e = row & 15;
    for (int d = threadIdx.x; d < Dn; d += 256)
        g_WT[row * 1024 + d] = src[d * En + e];
}

// ---------------- kernel 1: gating logits (4 rows, fused clean+noise) --------
__global__ __launch_bounds__(512, 4) void k_logits(
    const float* __restrict__ x, const float* __restrict__ noise)
{
    __shared__ float xs[4][1024];
    __shared__ float part_c[4][16];
    __shared__ float part_n[4][16];
    int tid = threadIdx.x;
    int b0 = blockIdx.x * 4;

    ((float4*)xs)[tid*2]   = ((const float4*)(x + (size_t)b0 * Dn))[tid*2];
    ((float4*)xs)[tid*2+1] = ((const float4*)(x + (size_t)b0 * Dn))[tid*2+1];
    __syncthreads();

    int w = tid >> 5, lane = tid & 31;
    const float4* Wg4 = (const float4*)(g_WT + w * 1024);
    const float4* Wn4 = (const float4*)(g_WT + (16 + w) * 1024);

    float sc[4] = {0.f,0.f,0.f,0.f};
    float sn[4] = {0.f,0.f,0.f,0.f};
    #pragma unroll
    for (int it = 0; it < 8; it++) {
        int q = it * 32 + lane;
        float4 wgv = Wg4[q];
        float4 wnv = Wn4[q];
        #pragma unroll
        for (int r = 0; r < 4; r++) {
            float4 xv = *(const float4*)&xs[r][q * 4];
            float dc = fmaf(xv.x, wgv.x, fmaf(xv.y, wgv.y, fmaf(xv.z, wgv.z, xv.w * wgv.w)));
            float dn = fmaf(xv.x, wnv.x, fmaf(xv.y, wnv.y, fmaf(xv.z, wnv.z, xv.w * wnv.w)));
            sc[r] += dc;
            sn[r] += dn;
        }
    }
    #pragma unroll
    for (int r = 0; r < 4; r++) {
        float vc = sc[r], vn = sn[r];
        #pragma unroll
        for (int off = 16; off; off >>= 1) {
            vc += __shfl_down_sync(0xffffffffu, vc, off);
            vn += __shfl_down_sync(0xffffffffu, vn, off);
        }
        if (lane == 0) { part_c[r][w] = vc; part_n[r][w] = vn; }
    }
    __syncthreads();

    if (tid < 64) {
        int r = tid >> 4, e2 = tid & 15;
        int b = b0 + r;
        float clean = part_c[r][e2];
        float raw   = part_n[r][e2];
        float sp = fmaxf(raw, 0.f) + log1pf(expf(-fabsf(raw)));
        float sd = sp + 0.01f;
        float nz = clean + noise[b * En + e2] * sd;
        g_clean[b * En + e2]  = clean;
        g_stddev[b * En + e2] = sd;
        g_noisy[b * En + e2]  = nz;
    }
}

// ---------------- kernel 2: softmax / top-9 / gates / load -------------------
__global__ __launch_bounds__(256) void k_gate()
{
    int b = blockIdx.x * 256 + threadIdx.x;
    int lane = threadIdx.x & 31;

    float nz[16], cl[16], sd[16];
    #pragma unroll
    for (int i = 0; i < 4; i++) {
        float4 v = ((const float4*)(g_noisy  + (size_t)b * 16))[i];
        nz[4*i] = v.x; nz[4*i+1] = v.y; nz[4*i+2] = v.z; nz[4*i+3] = v.w;
        float4 c = ((const float4*)(g_clean  + (size_t)b * 16))[i];
        cl[4*i] = c.x; cl[4*i+1] = c.y; cl[4*i+2] = c.z; cl[4*i+3] = c.w;
        float4 s = ((const float4*)(g_stddev + (size_t)b * 16))[i];
        sd[4*i] = s.x; sd[4*i+1] = s.y; sd[4*i+2] = s.z; sd[4*i+3] = s.w;
    }

    float m = nz[0];
    #pragma unroll
    for (int e = 1; e < 16; e++) m = fmaxf(m, nz[e]);
    float p[16], sum = 0.f;
    #pragma unroll
    for (int e = 0; e < 16; e++) { p[e] = expf(nz[e] - m); sum += p[e]; }
    float inv = 1.f / sum;
    #pragma unroll
    for (int e = 0; e < 16; e++) p[e] *= inv;

    float topv[9]; int topi[9]; unsigned mask = 0;
    #pragma unroll
    for (int t = 0; t < 9; t++) {
        float best = -1.f; int bi = 0;
        #pragma unroll
        for (int e = 0; e < 16; e++) {
            bool ok = (!((mask >> e) & 1u)) && (p[e] > best);
            if (ok) { best = p[e]; bi = e; }
        }
        topv[t] = best; topi[t] = bi; mask |= (1u << bi);
    }

    float ksum = 0.f;
    #pragma unroll
    for (int t = 0; t < 8; t++) ksum += topv[t];
    float dinv = 1.f / (ksum + 1e-6f);

    float g16[16];
    #pragma unroll
    for (int e = 0; e < 16; e++) {
        float ge = 0.f;
        #pragma unroll
        for (int t = 0; t < 8; t++) ge = (topi[t] == e) ? topv[t] * dinv : ge;
        g16[e] = ge;
    }
    #pragma unroll
    for (int i = 0; i < 4; i++)
        ((float4*)(g_gates + (size_t)b * 16))[i] =
            make_float4(g16[4*i], g16[4*i+1], g16[4*i+2], g16[4*i+3]);

    float thr_in = topv[8], thr_out = topv[7];
    float ldv[16];
    #pragma unroll
    for (int e = 0; e < 16; e++) {
        bool in = nz[e] > thr_in;
        float thr = in ? thr_in : thr_out;
        float z = (cl[e] - thr) / sd[e];
        ldv[e] = 0.5f * (1.f + erff(z * 0.70710678118654752440f));
    }
    #pragma unroll
    for (int e = 0; e < 16; e++) {
        float v1 = g16[e], v2 = ldv[e];
        #pragma unroll
        for (int off = 16; off; off >>= 1) {
            v1 += __shfl_down_sync(0xffffffffu, v1, off);
            v2 += __shfl_down_sync(0xffffffffu, v2, off);
        }
        if (lane == 0) {
            atomicAdd(&g_importance[e], v1);
            atomicAdd(&g_load[e], v2);
        }
    }
}

// ---------------- kernel 3: loss (off GEMM critical path) --------------------
__global__ void k_loss(float* __restrict__ out)
{
    if (threadIdx.x == 0 && blockIdx.x == 0) {
        float mi = 0.f, ml = 0.f;
        for (int e = 0; e < En; e++) { mi += g_importance[e]; ml += g_load[e]; }
        mi *= (1.f / En); ml *= (1.f / En);
        float vi = 0.f, vl = 0.f;
        for (int e = 0; e < En; e++) {
            float d1 = g_importance[e] - mi; vi += d1 * d1;
            float d2 = g_load[e] - ml;       vl += d2 * d2;
        }
        vi /= (En - 1); vl /= (En - 1);
        out[(size_t)Bn * Hn] = 0.01f * (vi / (mi * mi + 1e-10f) + vl / (ml * ml + 1e-10f));
    }
}

// ---------------- kernel 5: B = expert_w -> tf32, 32KB chunks, swizzled ------
__global__ __launch_bounds__(256) void k_prep_b(const float* __restrict__ ew)
{
#if HAS_TC
    int h64 = blockIdx.x;
    int kc  = blockIdx.y;
    __shared__ float ts[64][65];
    int tid = threadIdx.x;
    int kl = tid >> 4;
    int h4 = (tid & 15) * 4;
    #pragma unroll
    for (int r = 0; r < 4; r++) {
        int kk = kl + r * 16;
        float4 v = *(const float4*)(ew + (size_t)(kc * 64 + kk) * Hn + h64 * 64 + h4);
        ts[h4 + 0][kk] = v.x; ts[h4 + 1][kk] = v.y;
        ts[h4 + 2][kk] = v.z; ts[h4 + 3][kk] = v.w;
    }
    __syncthreads();
    #pragma unroll
    for (int r2 = 0; r2 < 2; r2++) {
        int it = tid + r2 * 256;
        int hl = it >> 3, kg = it & 7;
        uint32_t w[8];
        #pragma unroll
        for (int j = 0; j < 8; j++) w[j] = f2tf(ts[hl][kg * 8 + j]);
        int hg = h64 * 64 + hl;
        int ht = hg >> 8, rr = hg & 255;
        int ch32 = kc * 2 + (kg >> 2);
        uint32_t bytec = (uint32_t)((kg & 3) * 32);
        size_t base = ((size_t)(ht * TC_NCH + ch32)) * TC_BCH;
        *(uint4*)(g_Bt + base + SWZ((uint32_t)(rr * 128) + bytec))      = make_uint4(w[0], w[1], w[2], w[3]);
        *(uint4*)(g_Bt + base + SWZ((uint32_t)(rr * 128) + bytec + 16)) = make_uint4(w[4], w[5], w[6], w[7]);
    }
#endif
}

__global__ __launch_bounds__(256) void k_prep_bb(const float* __restrict__ eb)
{
#if HAS_TC
    int ht = blockIdx.x;
    int row = threadIdx.x;
    int hg = ht * 256 + row;
    #pragma unroll
    for (int kg = 0; kg < 4; kg++) {
        uint32_t w[8];
        #pragma unroll
        for (int j = 0; j < 8; j++) {
            int c = kg * 8 + j;
            w[j] = (c < 16) ? f2tf(eb[c * Hn + hg]) : 0u;
        }
        size_t base = ((size_t)(ht * TC_NCH + 512)) * TC_BCH;
        uint32_t bytec = (uint32_t)(kg * 32);
        *(uint4*)(g_Bt + base + SWZ((uint32_t)(row * 128) + bytec))      = make_uint4(w[0], w[1], w[2], w[3]);
        *(uint4*)(g_Bt + base + SWZ((uint32_t)(row * 128) + bytec + 16)) = make_uint4(w[4], w[5], w[6], w[7]);
    }
#endif
}

// =============================================================================
//  kernel 7 (tc path): fused tf32 GEMM, KC=32, 4-stage, 2-CTA B mcast
//  576 threads. Fused full-barrier per stage: count 17 (16 converter warps +
//  producer arrive.expect_tx + 32KB tx); issuer does ONE wait per chunk.
// =============================================================================
#define TC_MT 128
#define TC_NT 256
#define CSZ 2
#define CMASK ((uint16_t)0x3)
#define NST 4
#define SM_A(s)   (1024u + (uint32_t)(s) * 16384u)     // 1024..66560
#define SM_B(s)   (66560u + (uint32_t)(s) * 32768u)    // 66560..197632
#define SM_GS     197632u
#define GEMM2_SMEM 206848

__global__ __launch_bounds__(576, 1) __cluster_dims__(1, CSZ, 1)
void k_gemm_tc2(const float* __restrict__ x, float* __restrict__ out)
{
#if HAS_TC
    extern __shared__ unsigned char smc[];
    const uint32_t sb = smem_u32(smc);
    const uint32_t mb_f  = sb + 0;      // fused full barriers [4]
    const uint32_t mb_dn = sb + 64;     // done barriers [4]
    const uint32_t mb_done = sb + 96;
    const uint32_t tptr    = sb + 128;
    float* gs = (float*)(smc + SM_GS);

    const int tid = threadIdx.x, wid = tid >> 5, lane = tid & 31;
    const int nt = blockIdx.x, mt = blockIdx.y;
    const int bM = mt * TC_MT;
    const uint32_t rank = ctarank();

    if (tid == 0) {
        #pragma unroll
        for (int s = 0; s < NST; s++) {
            MBAR_INIT(mb_f + s * 8, 17);     // 16 converter warps + producer expect_tx
            MBAR_INIT(mb_dn + s * 8, CSZ);
        }
        MBAR_INIT(mb_done, CSZ);
    }
    for (int i = tid; i < TC_MT * En; i += 576) {
        int r = i >> 4, e = i & 15;
        gs[r * 17 + e] = g_gates[(size_t)(bM + r) * En + e];
    }
    __syncthreads();
    if (wid == 17) {
        asm volatile("tcgen05.alloc.cta_group::1.sync.aligned.shared::cta.b32 [%0], %1;" :: "r"(tptr), "r"((uint32_t)TC_NT) : "memory");
        asm volatile("tcgen05.relinquish_alloc_permit.cta_group::1.sync.aligned;");
    }
    __syncthreads();
    CLUSTER_SYNC();
    uint32_t tmem;
    asm volatile("ld.shared.b32 %0, [%1];" : "=r"(tmem) : "r"(tptr));

    const uint64_t DESC_BASE =
        (uint64_t(2) << 61) | (uint64_t(1) << 46) | (uint64_t(64) << 32) | (uint64_t(1) << 16);
    const uint32_t GIDESC = (1u<<4) | (2u<<7) | (2u<<10) | ((TC_NT/8u)<<17) | ((TC_MT/16u)<<24);

    if (tid < 512) {
        // ---- A converters: 8 values/thread/chunk, convert-before-wait ------
        const int r  = tid >> 2;            // row 0..127
        const int q4 = tid & 3;             // 8-col group within 32-col chunk
        const float* xp = x + (size_t)(bM + r) * Dn + (size_t)q4 * 8;
        const uint32_t rowb = (uint32_t)(r * 128 + q4 * 32);
        const uint32_t off0 = SWZ(rowb);
        const uint32_t off1 = SWZ(rowb + 16);
        const float* grow = gs + r * 17;
        uint32_t dph[NST] = {0, 0, 0, 0};
        int i = 0;
        for (int db = 0; db < 32; db++) {   // 32-col x blocks
            float xr[8];
            {
                const float4* xv = (const float4*)(xp + db * 32);
                float4 f0 = xv[0], f1 = xv[1];
                xr[0] = f0.x; xr[1] = f0.y; xr[2] = f0.z; xr[3] = f0.w;
                xr[4] = f1.x; xr[5] = f1.y; xr[6] = f1.z; xr[7] = f1.w;
            }
            for (int e = 0; e < 16; e++, i++) {
                int s = i & (NST - 1);
                float g = grow[e];
                uint32_t w[8];
                #pragma unroll
                for (int j = 0; j < 8; j++) w[j] = f2tf(g * xr[j]);
                if (i >= NST) { MBAR_WAIT(mb_dn + s * 8, dph[s]); dph[s] ^= 1; }
                unsigned char* ap = smc + SM_A(s);
                *(uint4*)(ap + off0) = make_uint4(w[0], w[1], w[2], w[3]);
                *(uint4*)(ap + off1) = make_uint4(w[4], w[5], w[6], w[7]);
                asm volatile("fence.proxy.async.shared::cta;" ::: "memory");
                __syncwarp();
                if (lane == 0) MBAR_ARRIVE(mb_f + s * 8);
            }
        }
        // bias chunk (i == 512): global cols 0..15 = gates, 16..31 = 0
        {
            int s = 0;
            uint32_t w[8];
            #pragma unroll
            for (int j = 0; j < 8; j++) {
                int c = q4 * 8 + j;
                w[j] = (c < 16) ? f2tf(grow[c]) : 0u;
            }
            MBAR_WAIT(mb_dn + s * 8, dph[s]); dph[s] ^= 1;
            unsigned char* ap = smc + SM_A(s);
            *(uint4*)(ap + off0) = make_uint4(w[0], w[1], w[2], w[3]);
            *(uint4*)(ap + off1) = make_uint4(w[4], w[5], w[6], w[7]);
            asm volatile("fence.proxy.async.shared::cta;" ::: "memory");
            __syncwarp();
            if (lane == 0) MBAR_ARRIVE(mb_f + s * 8);
        }
    } else if (tid == 512) {
        // ---- B producer: 2-way multicast cooperative halves ----------------
        const unsigned char* pBt = g_Bt + (size_t)nt * TC_NCH * TC_BCH;
        const uint32_t hoff = rank * 16384u;
        uint32_t dph[NST] = {0, 0, 0, 0};
        for (int i = 0; i <= 512; i++) {
            int s = i & (NST - 1);
            if (i >= NST) { MBAR_WAIT_RLX(mb_dn + s * 8, dph[s]); dph[s] ^= 1; }
            int cB = (i < 512) ? ((i & 15) * 32 + (i >> 4)) : 512;
            uint32_t mbf = mb_f + s * 8;
            MBAR_EXPECT_TX(mbf, TC_BCH);    // arrival #17 + 32KB tx
            bulk_g2s_mc(sb + SM_B(s) + hoff, pBt + (size_t)cB * TC_BCH + hoff, 16384u, mbf, CMASK);
        }
    } else if (tid == 544) {
        // ---- MMA issuer: single wait per chunk ------------------------------
        uint32_t fph[NST] = {0, 0, 0, 0};
        uint32_t acc = 0;
        for (int i = 0; i <= 512; i++) {
            int s = i & (NST - 1);
            MBAR_WAIT(mb_f + s * 8, fph[s]); fph[s] ^= 1;
            uint64_t da = DESC_BASE | ((uint64_t)((sb + SM_A(s)) >> 4) & 0x3FFF);
            uint64_t db = DESC_BASE | ((uint64_t)((sb + SM_B(s)) >> 4) & 0x3FFF);
            #pragma unroll
            for (int ks = 0; ks < 4; ks++) {
                asm volatile("{ .reg .pred p; setp.ne.u32 p, %5, 0;\n"
                    "tcgen05.mma.cta_group::1.kind::tf32 [%0], %1, %2, %3, {%4,%4,%4,%4}, p; }"
                    :: "r"(tmem), "l"(da + ks * 2), "l"(db + ks * 2), "r"(GIDESC), "r"(0u), "r"(acc) : "memory");
                acc = 1;
            }
            uint32_t mtarget = (i == 512) ? mb_done : (mb_dn + s * 8);
            asm volatile(
                "tcgen05.commit.cta_group::1.mbarrier::arrive::one.shared::cluster.multicast::cluster.b64 [%0], %1;"
                :: "r"(mtarget), "h"(CMASK) : "memory");
        }
    }

    // ---------------- epilogue -----------------------------------------------
    MBAR_WAIT(mb_done, 0);
    asm volatile("tcgen05.fence::after_thread_sync;" ::: "memory");

    if (wid < 4) {
        int row = bM + wid * 32 + lane;
        float* orow = out + (size_t)row * Hn + nt * TC_NT;
        #pragma unroll
        for (int cc = 0; cc < 8; cc++) {
            uint32_t r[32];
            asm volatile(
                "tcgen05.ld.sync.aligned.32x32b.x32.b32 "
                "{%0,%1,%2,%3,%4,%5,%6,%7,%8,%9,%10,%11,%12,%13,%14,%15,"
                "%16,%17,%18,%19,%20,%21,%22,%23,%24,%25,%26,%27,%28,%29,%30,%31}, [%32];"
                : "=r"(r[0]),"=r"(r[1]),"=r"(r[2]),"=r"(r[3]),"=r"(r[4]),"=r"(r[5]),"=r"(r[6]),"=r"(r[7]),
                  "=r"(r[8]),"=r"(r[9]),"=r"(r[10]),"=r"(r[11]),"=r"(r[12]),"=r"(r[13]),"=r"(r[14]),"=r"(r[15]),
                  "=r"(r[16]),"=r"(r[17]),"=r"(r[18]),"=r"(r[19]),"=r"(r[20]),"=r"(r[21]),"=r"(r[22]),"=r"(r[23]),
                  "=r"(r[24]),"=r"(r[25]),"=r"(r[26]),"=r"(r[27]),"=r"(r[28]),"=r"(r[29]),"=r"(r[30]),"=r"(r[31])
                : "r"(tmem + cc * 32));
            asm volatile("tcgen05.wait::ld.sync.aligned;" ::: "memory");
            #pragma unroll
            for (int q = 0; q < 8; q++) {
                *(float4*)(orow + cc * 32 + q * 4) = make_float4(
                    __uint_as_float(r[q*4+0]), __uint_as_float(r[q*4+1]),
                    __uint_as_float(r[q*4+2]), __uint_as_float(r[q*4+3]));
            }
        }
    }
    __syncthreads();
    if (wid == 17)
        asm volatile("tcgen05.dealloc.cta_group::1.sync.aligned.b32 %0, %1;" :: "r"(tmem), "r"((uint32_t)TC_NT));
    CLUSTER_SYNC();
#endif
}

// =============================================================================
//  PATH B: tf32 mma.sync GEMM fallback (base-target legal)
// =============================================================================
#define BM 128
#define BN 128
#define BK 32
#define STAGES 4
#define ASTR 44
#define BSTR 136
#define GSTR 17
#define A_ST_FLT (BM * ASTR)
#define B_ST_FLT (BK * BSTR)
#define NTILES (En * Dn / BK)

__global__ __launch_bounds__(256, 1) void k_gemm_mma(
    const float* __restrict__ x, const float* __restrict__ ew,
    const float* __restrict__ eb, float* __restrict__ out)
{
    if (g_tc) return;

    extern __shared__ float sm[];
    float* As  = sm;
    float* Bs  = sm + STAGES * A_ST_FLT;
    float* gs  = Bs + STAGES * B_ST_FLT;
    float* ebs = gs + BM * GSTR;

    const int tid  = threadIdx.x;
    const int lane = tid & 31;
    const int wid  = tid >> 5;
    const int wm   = wid >> 2;
    const int wn   = wid & 3;
    const int grp  = lane >> 2;
    const int qid  = lane & 3;
    const int bM = blockIdx.y * BM;
    const int bN = blockIdx.x * BN;

    for (int i = tid; i < BM * En; i += 256) {
        int r = i >> 4, e = i & 15;
        gs[r * GSTR + e] = g_gates[(size_t)(bM + r) * En + e];
    }
    for (int i = tid; i < En * BN; i += 256) {
        int e = i >> 7, c = i & 127;
        ebs[e * BN + c] = eb[(size_t)e * Hn + bN + c];
    }

    const uint32_t sbase = smem_u32(sm);
    const int ar = tid >> 1, ac = (tid & 1) * 4;
    const int bk0 = tid >> 5, bc0 = (tid & 31) * 4;
    const uint32_t adst0 = sbase + (uint32_t)(ar * ASTR + ac) * 4u;
    const uint32_t bdst0 = sbase + (uint32_t)(STAGES * A_ST_FLT + bk0 * BSTR + bc0) * 4u;

#define LOAD_TILE(kt, s) do {                                                   \
        int _d0 = ((kt) * BK) & (Dn - 1);                                       \
        cpa16(adst0 + (uint32_t)((s) * A_ST_FLT * 4),                           \
              x + (size_t)(bM + ar) * Dn + _d0 + ac);                           \
        const float* _bw = ew + (size_t)((kt) * BK + bk0) * Hn + bN + bc0;      \
        uint32_t _bd = bdst0 + (uint32_t)((s) * B_ST_FLT * 4);                  \
        cpa16(_bd,                      _bw);                                   \
        cpa16(_bd + 8u*BSTR*4u,         _bw + (size_t)8  * Hn);                 \
        cpa16(_bd + 16u*BSTR*4u,        _bw + (size_t)16 * Hn);                 \
        cpa16(_bd + 24u*BSTR*4u,        _bw + (size_t)24 * Hn);                 \
    } while (0)

    #pragma unroll
    for (int s = 0; s < STAGES - 1; s++) { LOAD_TILE(s, s); CPA_COMMIT(); }

    float acc[4][4][4];
    #pragma unroll
    for (int mi = 0; mi < 4; mi++)
        #pragma unroll
        for (int ni = 0; ni < 4; ni++)
            #pragma unroll
            for (int q = 0; q < 4; q++) acc[mi][ni][q] = 0.f;

    const int aoff = (wm * 64 + grp) * ASTR + qid;
    const int boff = qid * BSTR + wn * 32 + grp;

    float g0[4], g1[4];
    __syncthreads();

    for (int kt = 0; kt < NTILES; kt++) {
        CPA_WAIT2();
        __syncthreads();

        if ((kt & 31) == 0) {
            int e = kt >> 5;
            #pragma unroll
            for (int mi = 0; mi < 4; mi++) {
                g0[mi] = gs[(wm * 64 + mi * 16 + grp) * GSTR + e];
                g1[mi] = gs[(wm * 64 + mi * 16 + grp + 8) * GSTR + e];
            }
        }

        int nk = kt + STAGES - 1;
        if (nk < NTILES) LOAD_TILE(nk, nk & (STAGES - 1));
        CPA_COMMIT();

        const float* Ap = As + (kt & (STAGES - 1)) * A_ST_FLT + aoff;
        const float* Bp = Bs + (kt & (STAGES - 1)) * B_ST_FLT + boff;

        #pragma unroll
        for (int ks = 0; ks < 4; ks++) {
            uint32_t bf[4][2];
            #pragma unroll
            for (int ni = 0; ni < 4; ni++) {
                bf[ni][0] = f2tf(Bp[(ks * 8) * BSTR + ni * 8]);
                bf[ni][1] = f2tf(Bp[(ks * 8 + 4) * BSTR + ni * 8]);
            }
            #pragma unroll
            for (int mi = 0; mi < 4; mi++) {
                const float* ab = Ap + mi * 16 * ASTR + ks * 8;
                uint32_t a0 = f2tf(g0[mi] * ab[0]);
                uint32_t a1 = f2tf(g1[mi] * ab[8 * ASTR]);
                uint32_t a2 = f2tf(g0[mi] * ab[4]);
                uint32_t a3 = f2tf(g1[mi] * ab[8 * ASTR + 4]);
                #pragma unroll
                for (int ni = 0; ni < 4; ni++)
                    mma_tf32(acc[mi][ni], a0, a1, a2, a3, bf[ni][0], bf[ni][1]);
            }
        }
    }

    #pragma unroll
    for (int mi = 0; mi < 4; mi++) {
        int r0 = wm * 64 + mi * 16 + grp;
        #pragma unroll
        for (int e = 0; e < En; e++) {
            float ge0 = gs[r0 * GSTR + e];
            float ge1 = gs[(r0 + 8) * GSTR + e];
            #pragma unroll
            for (int ni = 0; ni < 4; ni++) {
                int c0 = wn * 32 + ni * 8 + 2 * qid;
                float b0v = ebs[e * BN + c0];
                float b1v = ebs[e * BN + c0 + 1];
                acc[mi][ni][0] = fmaf(ge0, b0v, acc[mi][ni][0]);
                acc[mi][ni][1] = fmaf(ge0, b1v, acc[mi][ni][1]);
                acc[mi][ni][2] = fmaf(ge1, b0v, acc[mi][ni][2]);
                acc[mi][ni][3] = fmaf(ge1, b1v, acc[mi][ni][3]);
            }
        }
    }

    #pragma unroll
    for (int mi = 0; mi < 4; mi++) {
        int r0 = bM + wm * 64 + mi * 16 + grp;
        #pragma unroll
        for (int ni = 0; ni < 4; ni++) {
            int c0 = bN + wn * 32 + ni * 8 + 2 * qid;
            *(float2*)(out + (size_t)r0 * Hn + c0)       = make_float2(acc[mi][ni][0], acc[mi][ni][1]);
            *(float2*)(out + (size_t)(r0 + 8) * Hn + c0) = make_float2(acc[mi][ni][2], acc[mi][ni][3]);
        }
    }
#undef LOAD_TILE
}

// ---------------- launch ------------------------------------------------------
extern "C" void kernel_launch(void* const* d_in, const int* in_sizes, int n_in,
                              void* d_out, int out_size)
{
    const float* x     = (const float*)d_in[0];
    const float* wg    = (const float*)d_in[1];
    const float* wn    = (const float*)d_in[2];
    const float* ew    = (const float*)d_in[3];
    const float* eb    = (const float*)d_in[4];
    const float* noise = (const float*)d_in[5];
    float* out = (float*)d_out;

    static const int MMA_SMEM = (STAGES * (A_ST_FLT + B_ST_FLT) + BM * GSTR + En * BN) * 4;
    static cudaStream_t s2 = nullptr, s3 = nullptr;
    static cudaEvent_t ev_fork = nullptr, ev_join = nullptr, ev_gate = nullptr, ev_loss = nullptr;
    if (!s2) {
        cudaStreamCreateWithFlags(&s2, cudaStreamNonBlocking);
        cudaStreamCreateWithFlags(&s3, cudaStreamNonBlocking);
        cudaEventCreateWithFlags(&ev_fork, cudaEventDisableTiming);
        cudaEventCreateWithFlags(&ev_join, cudaEventDisableTiming);
        cudaEventCreateWithFlags(&ev_gate, cudaEventDisableTiming);
        cudaEventCreateWithFlags(&ev_loss, cudaEventDisableTiming);
        cudaFuncSetAttribute(k_gemm_tc2, cudaFuncAttributeMaxDynamicSharedMemorySize, GEMM2_SMEM);
        cudaFuncSetAttribute(k_gemm_mma, cudaFuncAttributeMaxDynamicSharedMemorySize, MMA_SMEM);
    }

    k_init<<<1, 32>>>();
    k_prep_w<<<32, 256>>>(wg, wn);

    // fork: B preprocessing runs concurrently with the gating chain
    cudaEventRecord(ev_fork, 0);
    cudaStreamWaitEvent(s2, ev_fork, 0);
    k_prep_b<<<dim3(16, 256), 256, 0, s2>>>(ew);
    k_prep_bb<<<4, 256, 0, s2>>>(eb);
    cudaEventRecord(ev_join, s2);

    // gating chain (split kernels, R12 configuration)
    k_logits<<<Bn / 4, 512>>>(x, noise);
    k_gate<<<Bn / 256, 256>>>();

    // loss on s3 (off the GEMM critical path), joined back AFTER the GEMM
    cudaEventRecord(ev_gate, 0);
    cudaStreamWaitEvent(s3, ev_gate, 0);
    k_loss<<<1, 32, 0, s3>>>(out);
    cudaEventRecord(ev_loss, s3);

    // join prep, then GEMM
    cudaStreamWaitEvent(0, ev_join, 0);
    k_gemm_tc2<<<dim3(Hn / TC_NT, Bn / TC_MT), 576, GEMM2_SMEM>>>(x, out);

    // mma.sync fallback (early-exits if tc path is live)
    k_gemm_mma<<<dim3(Hn / BN, Bn / BM), 256, MMA_SMEM>>>(x, ew, eb, out);

    // rejoin s3 so the capture graph has no unjoined work
    cudaStreamWaitEvent(0, ev_loss, 0);
}

// round 16
// speedup vs baseline: 1.0530x; 1.0174x over previous
#include <cuda_runtime.h>
#include <cuda_bf16.h>
#include <math.h>
#include <stdint.h>

#define Bn 8192
#define Dn 1024
#define En 16
#define Hn 1024

// ---------- arch-feature gate for tcgen05 (compiles away on base sm_103) ----
#if defined(__CUDA_ARCH__) && (defined(__CUDA_ARCH_FEAT_SM103_ALL) || defined(__CUDA_ARCH_FEAT_SM100_ALL) || defined(__CUDA_ARCH_FAMILY_SPECIFIC__))
#define HAS_TC 1
#else
#define HAS_TC 0
#endif

// ---------------- scratch ---------------------------------------------------
__device__ float g_clean[Bn * En];
__device__ float g_stddev[Bn * En];
__device__ float g_noisy[Bn * En];
__device__ float g_gates[Bn * En];
__device__ float g_importance[En];
__device__ float g_load[En];
__device__ int   g_tc;
__device__ float g_WT[32 * 1024];   // rows 0-15: wg^T, rows 16-31: wn^T

// B operand: tf32, tiled [4 nt][513 ch][32KB]; chunk = 256 rows x 128B SW128
#define TC_NCH 513
#define TC_BCH 32768
__device__ __align__(1024) unsigned char g_Bt[(size_t)4 * TC_NCH * TC_BCH];

#define SWZ(b) ((b) ^ (((b) >> 3) & 0x70))

// ---------------- PTX helpers ------------------------------------------------
__device__ __forceinline__ uint32_t smem_u32(const void* p) {
    uint32_t a;
    asm("{ .reg .u64 t; cvta.to.shared.u64 t, %1; cvt.u32.u64 %0, t; }" : "=r"(a) : "l"(p));
    return a;
}
__device__ __forceinline__ uint32_t ctarank() {
    uint32_t r; asm("mov.u32 %0, %%cluster_ctarank;" : "=r"(r)); return r;
}
#define MBAR_INIT(a, c) asm volatile("mbarrier.init.shared.b64 [%0], %1;" :: "r"(a), "r"((uint32_t)(c)) : "memory")
#define MBAR_EXPECT_TX(a, n) asm volatile("mbarrier.arrive.expect_tx.shared.b64 _, [%0], %1;" :: "r"(a), "r"((uint32_t)(n)) : "memory")
#define MBAR_ARRIVE(a) asm volatile("mbarrier.arrive.shared.b64 _, [%0];" :: "r"(a) : "memory")
#define MBAR_WAIT(a, ph) do {                                                   \
    uint32_t _m = (a), _p = (ph), _d;                                           \
    asm volatile("{ .reg .pred p; mbarrier.try_wait.parity.acquire.cta.shared::cta.b64 p, [%1], %2; selp.b32 %0,1,0,p; }" \
        : "=r"(_d) : "r"(_m), "r"(_p) : "memory");                              \
    if (!_d) {                                                                  \
        asm volatile("{ .reg .pred P1; W%=: mbarrier.try_wait.parity.acquire.cta.shared::cta.b64 P1, [%0], %1, 0x989680; @P1 bra.uni D%=; bra.uni W%=; D%=: }" \
            :: "r"(_m), "r"(_p) : "memory");                                    \
    }                                                                           \
} while (0)
#define MBAR_WAIT_RLX(a, ph) do {                                               \
    uint32_t _m = (a), _p = (ph), _d;                                           \
    asm volatile("{ .reg .pred p; mbarrier.try_wait.parity.relaxed.cta.shared::cta.b64 p, [%1], %2, 0x989680; selp.b32 %0,1,0,p; }" \
        : "=r"(_d) : "r"(_m), "r"(_p) : "memory");                              \
    if (!_d) {                                                                  \
        asm volatile("{ .reg .pred P1; W%=: mbarrier.try_wait.parity.relaxed.cta.shared::cta.b64 P1, [%0], %1, 0x989680; @P1 bra.uni D%=; bra.uni W%=; D%=: }" \
            :: "r"(_m), "r"(_p) : "memory");                                    \
    }                                                                           \
} while (0)
#define CLUSTER_SYNC() do {                                                     \
    asm volatile("barrier.cluster.arrive.aligned;" ::: "memory");               \
    asm volatile("barrier.cluster.wait.aligned;" ::: "memory");                 \
} while (0)

__device__ __forceinline__ void bulk_g2s_mc(uint32_t dst, const void* src, uint32_t bytes,
                                            uint32_t mbar, uint16_t mask) {
    asm volatile("cp.async.bulk.shared::cluster.global.mbarrier::complete_tx::bytes.multicast::cluster "
        "[%0], [%1], %2, [%3], %4;"
        :: "r"(dst), "l"(src), "r"(bytes), "r"(mbar), "h"(mask) : "memory");
}
__device__ __forceinline__ void cpa16(uint32_t d, const void* s) {
    asm volatile("cp.async.cg.shared.global [%0], [%1], 16;" :: "r"(d), "l"(s) : "memory");
}
#define CPA_COMMIT() asm volatile("cp.async.commit_group;" ::: "memory")
#define CPA_WAIT2()  asm volatile("cp.async.wait_group 2;" ::: "memory")

__device__ __forceinline__ uint32_t f2tf(float v) {
    uint32_t r; asm("cvt.rna.tf32.f32 %0, %1;" : "=r"(r) : "f"(v)); return r;
}
__device__ __forceinline__ void mma_tf32(float* c, uint32_t a0, uint32_t a1, uint32_t a2, uint32_t a3,
                                         uint32_t b0, uint32_t b1) {
    asm volatile("mma.sync.aligned.m16n8k8.row.col.f32.tf32.tf32.f32 "
        "{%0,%1,%2,%3},{%4,%5,%6,%7},{%8,%9},{%0,%1,%2,%3};"
        : "+f"(c[0]), "+f"(c[1]), "+f"(c[2]), "+f"(c[3])
        : "r"(a0), "r"(a1), "r"(a2), "r"(a3), "r"(b0), "r"(b1));
}

// ---------------- kernel 0: init ---------------------------------------------
__global__ void k_init() {
    int t = threadIdx.x;
    if (t < En) { g_importance[t] = 0.f; g_load[t] = 0.f; }
    if (t == 0) g_tc = HAS_TC;
}

// ---------------- kernel 0b: transpose gate weights --------------------------
__global__ __launch_bounds__(256) void k_prep_w(
    const float* __restrict__ wg, const float* __restrict__ wn)
{
    int row = blockIdx.x;
    const float* src = (row < 16) ? wg : wn;
    int e = row & 15;
    for (int d = threadIdx.x; d < Dn; d += 256)
        g_WT[row * 1024 + d] = src[d * En + e];
}

// ---------------- kernel 1: gating logits (4 rows, fused clean+noise) --------
__global__ __launch_bounds__(512, 4) void k_logits(
    const float* __restrict__ x, const float* __restrict__ noise)
{
    __shared__ float xs[4][1024];
    __shared__ float part_c[4][16];
    __shared__ float part_n[4][16];
    int tid = threadIdx.x;
    int b0 = blockIdx.x * 4;

    ((float4*)xs)[tid*2]   = ((const float4*)(x + (size_t)b0 * Dn))[tid*2];
    ((float4*)xs)[tid*2+1] = ((const float4*)(x + (size_t)b0 * Dn))[tid*2+1];
    __syncthreads();

    int w = tid >> 5, lane = tid & 31;
    const float4* Wg4 = (const float4*)(g_WT + w * 1024);
    const float4* Wn4 = (const float4*)(g_WT + (16 + w) * 1024);

    float sc[4] = {0.f,0.f,0.f,0.f};
    float sn[4] = {0.f,0.f,0.f,0.f};
    #pragma unroll
    for (int it = 0; it < 8; it++) {
        int q = it * 32 + lane;
        float4 wgv = Wg4[q];
        float4 wnv = Wn4[q];
        #pragma unroll
        for (int r = 0; r < 4; r++) {
            float4 xv = *(const float4*)&xs[r][q * 4];
            float dc = fmaf(xv.x, wgv.x, fmaf(xv.y, wgv.y, fmaf(xv.z, wgv.z, xv.w * wgv.w)));
            float dn = fmaf(xv.x, wnv.x, fmaf(xv.y, wnv.y, fmaf(xv.z, wnv.z, xv.w * wnv.w)));
            sc[r] += dc;
            sn[r] += dn;
        }
    }
    #pragma unroll
    for (int r = 0; r < 4; r++) {
        float vc = sc[r], vn = sn[r];
        #pragma unroll
        for (int off = 16; off; off >>= 1) {
            vc += __shfl_down_sync(0xffffffffu, vc, off);
            vn += __shfl_down_sync(0xffffffffu, vn, off);
        }
        if (lane == 0) { part_c[r][w] = vc; part_n[r][w] = vn; }
    }
    __syncthreads();

    if (tid < 64) {
        int r = tid >> 4, e2 = tid & 15;
        int b = b0 + r;
        float clean = part_c[r][e2];
        float raw   = part_n[r][e2];
        float sp = fmaxf(raw, 0.f) + log1pf(expf(-fabsf(raw)));
        float sd = sp + 0.01f;
        float nz = clean + noise[b * En + e2] * sd;
        g_clean[b * En + e2]  = clean;
        g_stddev[b * En + e2] = sd;
        g_noisy[b * En + e2]  = nz;
    }
}

// ---------------- kernel 2: softmax / top-9 / gates / load -------------------
__global__ __launch_bounds__(256) void k_gate()
{
    int b = blockIdx.x * 256 + threadIdx.x;
    int lane = threadIdx.x & 31;

    float nz[16], cl[16], sd[16];
    #pragma unroll
    for (int i = 0; i < 4; i++) {
        float4 v = ((const float4*)(g_noisy  + (size_t)b * 16))[i];
        nz[4*i] = v.x; nz[4*i+1] = v.y; nz[4*i+2] = v.z; nz[4*i+3] = v.w;
        float4 c = ((const float4*)(g_clean  + (size_t)b * 16))[i];
        cl[4*i] = c.x; cl[4*i+1] = c.y; cl[4*i+2] = c.z; cl[4*i+3] = c.w;
        float4 s = ((const float4*)(g_stddev + (size_t)b * 16))[i];
        sd[4*i] = s.x; sd[4*i+1] = s.y; sd[4*i+2] = s.z; sd[4*i+3] = s.w;
    }

    float m = nz[0];
    #pragma unroll
    for (int e = 1; e < 16; e++) m = fmaxf(m, nz[e]);
    float p[16], sum = 0.f;
    #pragma unroll
    for (int e = 0; e < 16; e++) { p[e] = expf(nz[e] - m); sum += p[e]; }
    float inv = 1.f / sum;
    #pragma unroll
    for (int e = 0; e < 16; e++) p[e] *= inv;

    float topv[9]; int topi[9]; unsigned mask = 0;
    #pragma unroll
    for (int t = 0; t < 9; t++) {
        float best = -1.f; int bi = 0;
        #pragma unroll
        for (int e = 0; e < 16; e++) {
            bool ok = (!((mask >> e) & 1u)) && (p[e] > best);
            if (ok) { best = p[e]; bi = e; }
        }
        topv[t] = best; topi[t] = bi; mask |= (1u << bi);
    }

    float ksum = 0.f;
    #pragma unroll
    for (int t = 0; t < 8; t++) ksum += topv[t];
    float dinv = 1.f / (ksum + 1e-6f);

    float g16[16];
    #pragma unroll
    for (int e = 0; e < 16; e++) {
        float ge = 0.f;
        #pragma unroll
        for (int t = 0; t < 8; t++) ge = (topi[t] == e) ? topv[t] * dinv : ge;
        g16[e] = ge;
    }
    #pragma unroll
    for (int i = 0; i < 4; i++)
        ((float4*)(g_gates + (size_t)b * 16))[i] =
            make_float4(g16[4*i], g16[4*i+1], g16[4*i+2], g16[4*i+3]);

    float thr_in = topv[8], thr_out = topv[7];
    float ldv[16];
    #pragma unroll
    for (int e = 0; e < 16; e++) {
        bool in = nz[e] > thr_in;
        float thr = in ? thr_in : thr_out;
        float z = (cl[e] - thr) / sd[e];
        ldv[e] = 0.5f * (1.f + erff(z * 0.70710678118654752440f));
    }
    #pragma unroll
    for (int e = 0; e < 16; e++) {
        float v1 = g16[e], v2 = ldv[e];
        #pragma unroll
        for (int off = 16; off; off >>= 1) {
            v1 += __shfl_down_sync(0xffffffffu, v1, off);
            v2 += __shfl_down_sync(0xffffffffu, v2, off);
        }
        if (lane == 0) {
            atomicAdd(&g_importance[e], v1);
            atomicAdd(&g_load[e], v2);
        }
    }
}

// ---------------- kernel 3: loss (off GEMM critical path) --------------------
__global__ void k_loss(float* __restrict__ out)
{
    if (threadIdx.x == 0 && blockIdx.x == 0) {
        float mi = 0.f, ml = 0.f;
        for (int e = 0; e < En; e++) { mi += g_importance[e]; ml += g_load[e]; }
        mi *= (1.f / En); ml *= (1.f / En);
        float vi = 0.f, vl = 0.f;
        for (int e = 0; e < En; e++) {
            float d1 = g_importance[e] - mi; vi += d1 * d1;
            float d2 = g_load[e] - ml;       vl += d2 * d2;
        }
        vi /= (En - 1); vl /= (En - 1);
        out[(size_t)Bn * Hn] = 0.01f * (vi / (mi * mi + 1e-10f) + vl / (ml * ml + 1e-10f));
    }
}

// ---------------- kernel 5: B = expert_w -> tf32, 32KB chunks, swizzled ------
__global__ __launch_bounds__(256) void k_prep_b(const float* __restrict__ ew)
{
#if HAS_TC
    int h64 = blockIdx.x;
    int kc  = blockIdx.y;
    __shared__ float ts[64][65];
    int tid = threadIdx.x;
    int kl = tid >> 4;
    int h4 = (tid & 15) * 4;
    #pragma unroll
    for (int r = 0; r < 4; r++) {
        int kk = kl + r * 16;
        float4 v = *(const float4*)(ew + (size_t)(kc * 64 + kk) * Hn + h64 * 64 + h4);
        ts[h4 + 0][kk] = v.x; ts[h4 + 1][kk] = v.y;
        ts[h4 + 2][kk] = v.z; ts[h4 + 3][kk] = v.w;
    }
    __syncthreads();
    #pragma unroll
    for (int r2 = 0; r2 < 2; r2++) {
        int it = tid + r2 * 256;
        int hl = it >> 3, kg = it & 7;
        uint32_t w[8];
        #pragma unroll
        for (int j = 0; j < 8; j++) w[j] = f2tf(ts[hl][kg * 8 + j]);
        int hg = h64 * 64 + hl;
        int ht = hg >> 8, rr = hg & 255;
        int ch32 = kc * 2 + (kg >> 2);
        uint32_t bytec = (uint32_t)((kg & 3) * 32);
        size_t base = ((size_t)(ht * TC_NCH + ch32)) * TC_BCH;
        *(uint4*)(g_Bt + base + SWZ((uint32_t)(rr * 128) + bytec))      = make_uint4(w[0], w[1], w[2], w[3]);
        *(uint4*)(g_Bt + base + SWZ((uint32_t)(rr * 128) + bytec + 16)) = make_uint4(w[4], w[5], w[6], w[7]);
    }
#endif
}

__global__ __launch_bounds__(256) void k_prep_bb(const float* __restrict__ eb)
{
#if HAS_TC
    int ht = blockIdx.x;
    int row = threadIdx.x;
    int hg = ht * 256 + row;
    #pragma unroll
    for (int kg = 0; kg < 4; kg++) {
        uint32_t w[8];
        #pragma unroll
        for (int j = 0; j < 8; j++) {
            int c = kg * 8 + j;
            w[j] = (c < 16) ? f2tf(eb[c * Hn + hg]) : 0u;
        }
        size_t base = ((size_t)(ht * TC_NCH + 512)) * TC_BCH;
        uint32_t bytec = (uint32_t)(kg * 32);
        *(uint4*)(g_Bt + base + SWZ((uint32_t)(row * 128) + bytec))      = make_uint4(w[0], w[1], w[2], w[3]);
        *(uint4*)(g_Bt + base + SWZ((uint32_t)(row * 128) + bytec + 16)) = make_uint4(w[4], w[5], w[6], w[7]);
    }
#endif
}

// =============================================================================
//  kernel 7 (tc path): fused tf32 GEMM, KC=32, NST=2, OCCUPANCY 2 per SM.
//  Each CTA: 106KB smem + 256 TMEM cols -> two CTAs co-resident per SM;
//  sibling CTA's MMAs fill this CTA's pipeline bubbles. All 256 CTAs resident.
// =============================================================================
#define TC_MT 128
#define TC_NT 256
#define CSZ 2
#define CMASK ((uint16_t)0x3)
#define NST 2
#define SM_A(s)   (1024u  + (uint32_t)(s) * 16384u)    // 1024..33792
#define SM_B(s)   (33792u + (uint32_t)(s) * 32768u)    // 33792..99328
#define SM_GS     99328u
#define GEMM2_SMEM 108032

__global__ __launch_bounds__(576, 2) __cluster_dims__(1, CSZ, 1)
void k_gemm_tc2(const float* __restrict__ x, float* __restrict__ out)
{
#if HAS_TC
    extern __shared__ unsigned char smc[];
    const uint32_t sb = smem_u32(smc);
    const uint32_t mb_f  = sb + 0;      // fused full barriers [2]
    const uint32_t mb_dn = sb + 32;     // done barriers [2]
    const uint32_t mb_done = sb + 64;
    const uint32_t tptr    = sb + 128;
    float* gs = (float*)(smc + SM_GS);

    const int tid = threadIdx.x, wid = tid >> 5, lane = tid & 31;
    const int nt = blockIdx.x, mt = blockIdx.y;
    const int bM = mt * TC_MT;
    const uint32_t rank = ctarank();

    if (tid == 0) {
        #pragma unroll
        for (int s = 0; s < NST; s++) {
            MBAR_INIT(mb_f + s * 8, 17);     // 16 converter warps + producer expect_tx
            MBAR_INIT(mb_dn + s * 8, CSZ);
        }
        MBAR_INIT(mb_done, CSZ);
    }
    for (int i = tid; i < TC_MT * En; i += 576) {
        int r = i >> 4, e = i & 15;
        gs[r * 17 + e] = g_gates[(size_t)(bM + r) * En + e];
    }
    __syncthreads();
    if (wid == 17) {
        asm volatile("tcgen05.alloc.cta_group::1.sync.aligned.shared::cta.b32 [%0], %1;" :: "r"(tptr), "r"((uint32_t)TC_NT) : "memory");
        asm volatile("tcgen05.relinquish_alloc_permit.cta_group::1.sync.aligned;");
    }
    __syncthreads();
    CLUSTER_SYNC();
    uint32_t tmem;
    asm volatile("ld.shared.b32 %0, [%1];" : "=r"(tmem) : "r"(tptr));

    const uint64_t DESC_BASE =
        (uint64_t(2) << 61) | (uint64_t(1) << 46) | (uint64_t(64) << 32) | (uint64_t(1) << 16);
    const uint32_t GIDESC = (1u<<4) | (2u<<7) | (2u<<10) | ((TC_NT/8u)<<17) | ((TC_MT/16u)<<24);

    if (tid < 512) {
        // ---- A converters: 8 values/thread/chunk, convert-before-wait ------
        const int r  = tid >> 2;            // row 0..127
        const int q4 = tid & 3;             // 8-col group within 32-col chunk
        const float* xp = x + (size_t)(bM + r) * Dn + (size_t)q4 * 8;
        const uint32_t rowb = (uint32_t)(r * 128 + q4 * 32);
        const uint32_t off0 = SWZ(rowb);
        const uint32_t off1 = SWZ(rowb + 16);
        const float* grow = gs + r * 17;
        uint32_t dph[NST] = {0, 0};
        int i = 0;
        for (int db = 0; db < 32; db++) {   // 32-col x blocks
            float xr[8];
            {
                const float4* xv = (const float4*)(xp + db * 32);
                float4 f0 = xv[0], f1 = xv[1];
                xr[0] = f0.x; xr[1] = f0.y; xr[2] = f0.z; xr[3] = f0.w;
                xr[4] = f1.x; xr[5] = f1.y; xr[6] = f1.z; xr[7] = f1.w;
            }
            for (int e = 0; e < 16; e++, i++) {
                int s = i & (NST - 1);
                float g = grow[e];
                uint32_t w[8];
                #pragma unroll
                for (int j = 0; j < 8; j++) w[j] = f2tf(g * xr[j]);
                if (i >= NST) { MBAR_WAIT(mb_dn + s * 8, dph[s]); dph[s] ^= 1; }
                unsigned char* ap = smc + SM_A(s);
                *(uint4*)(ap + off0) = make_uint4(w[0], w[1], w[2], w[3]);
                *(uint4*)(ap + off1) = make_uint4(w[4], w[5], w[6], w[7]);
                asm volatile("fence.proxy.async.shared::cta;" ::: "memory");
                __syncwarp();
                if (lane == 0) MBAR_ARRIVE(mb_f + s * 8);
            }
        }
        // bias chunk (i == 512): global cols 0..15 = gates, 16..31 = 0
        {
            int s = 512 & (NST - 1);   // 0
            uint32_t w[8];
            #pragma unroll
            for (int j = 0; j < 8; j++) {
                int c = q4 * 8 + j;
                w[j] = (c < 16) ? f2tf(grow[c]) : 0u;
            }
            MBAR_WAIT(mb_dn + s * 8, dph[s]); dph[s] ^= 1;
            unsigned char* ap = smc + SM_A(s);
            *(uint4*)(ap + off0) = make_uint4(w[0], w[1], w[2], w[3]);
            *(uint4*)(ap + off1) = make_uint4(w[4], w[5], w[6], w[7]);
            asm volatile("fence.proxy.async.shared::cta;" ::: "memory");
            __syncwarp();
            if (lane == 0) MBAR_ARRIVE(mb_f + s * 8);
        }
    } else if (tid == 512) {
        // ---- B producer: 2-way multicast cooperative halves ----------------
        const unsigned char* pBt = g_Bt + (size_t)nt * TC_NCH * TC_BCH;
        const uint32_t hoff = rank * 16384u;
        uint32_t dph[NST] = {0, 0};
        for (int i = 0; i <= 512; i++) {
            int s = i & (NST - 1);
            if (i >= NST) { MBAR_WAIT_RLX(mb_dn + s * 8, dph[s]); dph[s] ^= 1; }
            int cB = (i < 512) ? ((i & 15) * 32 + (i >> 4)) : 512;
            uint32_t mbf = mb_f + s * 8;
            MBAR_EXPECT_TX(mbf, TC_BCH);    // arrival #17 + 32KB tx
            bulk_g2s_mc(sb + SM_B(s) + hoff, pBt + (size_t)cB * TC_BCH + hoff, 16384u, mbf, CMASK);
        }
    } else if (tid == 544) {
        // ---- MMA issuer: single wait per chunk ------------------------------
        uint32_t fph[NST] = {0, 0};
        uint32_t acc = 0;
        for (int i = 0; i <= 512; i++) {
            int s = i & (NST - 1);
            MBAR_WAIT(mb_f + s * 8, fph[s]); fph[s] ^= 1;
            uint64_t da = DESC_BASE | ((uint64_t)((sb + SM_A(s)) >> 4) & 0x3FFF);
            uint64_t db = DESC_BASE | ((uint64_t)((sb + SM_B(s)) >> 4) & 0x3FFF);
            #pragma unroll
            for (int ks = 0; ks < 4; ks++) {
                asm volatile("{ .reg .pred p; setp.ne.u32 p, %5, 0;\n"
                    "tcgen05.mma.cta_group::1.kind::tf32 [%0], %1, %2, %3, {%4,%4,%4,%4}, p; }"
                    :: "r"(tmem), "l"(da + ks * 2), "l"(db + ks * 2), "r"(GIDESC), "r"(0u), "r"(acc) : "memory");
                acc = 1;
            }
            uint32_t mtarget = (i == 512) ? mb_done : (mb_dn + s * 8);
            asm volatile(
                "tcgen05.commit.cta_group::1.mbarrier::arrive::one.shared::cluster.multicast::cluster.b64 [%0], %1;"
                :: "r"(mtarget), "h"(CMASK) : "memory");
        }
    }

    // ---------------- epilogue -----------------------------------------------
    MBAR_WAIT(mb_done, 0);
    asm volatile("tcgen05.fence::after_thread_sync;" ::: "memory");

    if (wid < 4) {
        int row = bM + wid * 32 + lane;
        float* orow = out + (size_t)row * Hn + nt * TC_NT;
        #pragma unroll
        for (int cc = 0; cc < 8; cc++) {
            uint32_t r[32];
            asm volatile(
                "tcgen05.ld.sync.aligned.32x32b.x32.b32 "
                "{%0,%1,%2,%3,%4,%5,%6,%7,%8,%9,%10,%11,%12,%13,%14,%15,"
                "%16,%17,%18,%19,%20,%21,%22,%23,%24,%25,%26,%27,%28,%29,%30,%31}, [%32];"
                : "=r"(r[0]),"=r"(r[1]),"=r"(r[2]),"=r"(r[3]),"=r"(r[4]),"=r"(r[5]),"=r"(r[6]),"=r"(r[7]),
                  "=r"(r[8]),"=r"(r[9]),"=r"(r[10]),"=r"(r[11]),"=r"(r[12]),"=r"(r[13]),"=r"(r[14]),"=r"(r[15]),
                  "=r"(r[16]),"=r"(r[17]),"=r"(r[18]),"=r"(r[19]),"=r"(r[20]),"=r"(r[21]),"=r"(r[22]),"=r"(r[23]),
                  "=r"(r[24]),"=r"(r[25]),"=r"(r[26]),"=r"(r[27]),"=r"(r[28]),"=r"(r[29]),"=r"(r[30]),"=r"(r[31])
                : "r"(tmem + cc * 32));
            asm volatile("tcgen05.wait::ld.sync.aligned;" ::: "memory");
            #pragma unroll
            for (int q = 0; q < 8; q++) {
                *(float4*)(orow + cc * 32 + q * 4) = make_float4(
                    __uint_as_float(r[q*4+0]), __uint_as_float(r[q*4+1]),
                    __uint_as_float(r[q*4+2]), __uint_as_float(r[q*4+3]));
            }
        }
    }
    __syncthreads();
    if (wid == 17)
        asm volatile("tcgen05.dealloc.cta_group::1.sync.aligned.b32 %0, %1;" :: "r"(tmem), "r"((uint32_t)TC_NT));
    CLUSTER_SYNC();
#endif
}

// =============================================================================
//  PATH B: tf32 mma.sync GEMM fallback (base-target legal)
// =============================================================================
#define BM 128
#define BN 128
#define BK 32
#define STAGES 4
#define ASTR 44
#define BSTR 136
#define GSTR 17
#define A_ST_FLT (BM * ASTR)
#define B_ST_FLT (BK * BSTR)
#define NTILES (En * Dn / BK)

__global__ __launch_bounds__(256, 1) void k_gemm_mma(
    const float* __restrict__ x, const float* __restrict__ ew,
    const float* __restrict__ eb, float* __restrict__ out)
{
    if (g_tc) return;

    extern __shared__ float sm[];
    float* As  = sm;
    float* Bs  = sm + STAGES * A_ST_FLT;
    float* gs  = Bs + STAGES * B_ST_FLT;
    float* ebs = gs + BM * GSTR;

    const int tid  = threadIdx.x;
    const int lane = tid & 31;
    const int wid  = tid >> 5;
    const int wm   = wid >> 2;
    const int wn   = wid & 3;
    const int grp  = lane >> 2;
    const int qid  = lane & 3;
    const int bM = blockIdx.y * BM;
    const int bN = blockIdx.x * BN;

    for (int i = tid; i < BM * En; i += 256) {
        int r = i >> 4, e = i & 15;
        gs[r * GSTR + e] = g_gates[(size_t)(bM + r) * En + e];
    }
    for (int i = tid; i < En * BN; i += 256) {
        int e = i >> 7, c = i & 127;
        ebs[e * BN + c] = eb[(size_t)e * Hn + bN + c];
    }

    const uint32_t sbase = smem_u32(sm);
    const int ar = tid >> 1, ac = (tid & 1) * 4;
    const int bk0 = tid >> 5, bc0 = (tid & 31) * 4;
    const uint32_t adst0 = sbase + (uint32_t)(ar * ASTR + ac) * 4u;
    const uint32_t bdst0 = sbase + (uint32_t)(STAGES * A_ST_FLT + bk0 * BSTR + bc0) * 4u;

#define LOAD_TILE(kt, s) do {                                                   \
        int _d0 = ((kt) * BK) & (Dn - 1);                                       \
        cpa16(adst0 + (uint32_t)((s) * A_ST_FLT * 4),                           \
              x + (size_t)(bM + ar) * Dn + _d0 + ac);                           \
        const float* _bw = ew + (size_t)((kt) * BK + bk0) * Hn + bN + bc0;      \
        uint32_t _bd = bdst0 + (uint32_t)((s) * B_ST_FLT * 4);                  \
        cpa16(_bd,                      _bw);                                   \
        cpa16(_bd + 8u*BSTR*4u,         _bw + (size_t)8  * Hn);                 \
        cpa16(_bd + 16u*BSTR*4u,        _bw + (size_t)16 * Hn);                 \
        cpa16(_bd + 24u*BSTR*4u,        _bw + (size_t)24 * Hn);                 \
    } while (0)

    #pragma unroll
    for (int s = 0; s < STAGES - 1; s++) { LOAD_TILE(s, s); CPA_COMMIT(); }

    float acc[4][4][4];
    #pragma unroll
    for (int mi = 0; mi < 4; mi++)
        #pragma unroll
        for (int ni = 0; ni < 4; ni++)
            #pragma unroll
            for (int q = 0; q < 4; q++) acc[mi][ni][q] = 0.f;

    const int aoff = (wm * 64 + grp) * ASTR + qid;
    const int boff = qid * BSTR + wn * 32 + grp;

    float g0[4], g1[4];
    __syncthreads();

    for (int kt = 0; kt < NTILES; kt++) {
        CPA_WAIT2();
        __syncthreads();

        if ((kt & 31) == 0) {
            int e = kt >> 5;
            #pragma unroll
            for (int mi = 0; mi < 4; mi++) {
                g0[mi] = gs[(wm * 64 + mi * 16 + grp) * GSTR + e];
                g1[mi] = gs[(wm * 64 + mi * 16 + grp + 8) * GSTR + e];
            }
        }

        int nk = kt + STAGES - 1;
        if (nk < NTILES) LOAD_TILE(nk, nk & (STAGES - 1));
        CPA_COMMIT();

        const float* Ap = As + (kt & (STAGES - 1)) * A_ST_FLT + aoff;
        const float* Bp = Bs + (kt & (STAGES - 1)) * B_ST_FLT + boff;

        #pragma unroll
        for (int ks = 0; ks < 4; ks++) {
            uint32_t bf[4][2];
            #pragma unroll
            for (int ni = 0; ni < 4; ni++) {
                bf[ni][0] = f2tf(Bp[(ks * 8) * BSTR + ni * 8]);
                bf[ni][1] = f2tf(Bp[(ks * 8 + 4) * BSTR + ni * 8]);
            }
            #pragma unroll
            for (int mi = 0; mi < 4; mi++) {
                const float* ab = Ap + mi * 16 * ASTR + ks * 8;
                uint32_t a0 = f2tf(g0[mi] * ab[0]);
                uint32_t a1 = f2tf(g1[mi] * ab[8 * ASTR]);
                uint32_t a2 = f2tf(g0[mi] * ab[4]);
                uint32_t a3 = f2tf(g1[mi] * ab[8 * ASTR + 4]);
                #pragma unroll
                for (int ni = 0; ni < 4; ni++)
                    mma_tf32(acc[mi][ni], a0, a1, a2, a3, bf[ni][0], bf[ni][1]);
            }
        }
    }

    #pragma unroll
    for (int mi = 0; mi < 4; mi++) {
        int r0 = wm * 64 + mi * 16 + grp;
        #pragma unroll
        for (int e = 0; e < En; e++) {
            float ge0 = gs[r0 * GSTR + e];
            float ge1 = gs[(r0 + 8) * GSTR + e];
            #pragma unroll
            for (int ni = 0; ni < 4; ni++) {
                int c0 = wn * 32 + ni * 8 + 2 * qid;
                float b0v = ebs[e * BN + c0];
                float b1v = ebs[e * BN + c0 + 1];
                acc[mi][ni][0] = fmaf(ge0, b0v, acc[mi][ni][0]);
                acc[mi][ni][1] = fmaf(ge0, b1v, acc[mi][ni][1]);
                acc[mi][ni][2] = fmaf(ge1, b0v, acc[mi][ni][2]);
                acc[mi][ni][3] = fmaf(ge1, b1v, acc[mi][ni][3]);
            }
        }
    }

    #pragma unroll
    for (int mi = 0; mi < 4; mi++) {
        int r0 = bM + wm * 64 + mi * 16 + grp;
        #pragma unroll
        for (int ni = 0; ni < 4; ni++) {
            int c0 = bN + wn * 32 + ni * 8 + 2 * qid;
            *(float2*)(out + (size_t)r0 * Hn + c0)       = make_float2(acc[mi][ni][0], acc[mi][ni][1]);
            *(float2*)(out + (size_t)(r0 + 8) * Hn + c0) = make_float2(acc[mi][ni][2], acc[mi][ni][3]);
        }
    }
#undef LOAD_TILE
}

// ---------------- launch ------------------------------------------------------
extern "C" void kernel_launch(void* const* d_in, const int* in_sizes, int n_in,
                              void* d_out, int out_size)
{
    const float* x     = (const float*)d_in[0];
    const float* wg    = (const float*)d_in[1];
    const float* wn    = (const float*)d_in[2];
    const float* ew    = (const float*)d_in[3];
    const float* eb    = (const float*)d_in[4];
    const float* noise = (const float*)d_in[5];
    float* out = (float*)d_out;

    static const int MMA_SMEM = (STAGES * (A_ST_FLT + B_ST_FLT) + BM * GSTR + En * BN) * 4;
    static cudaStream_t s2 = nullptr, s3 = nullptr;
    static cudaEvent_t ev_fork = nullptr, ev_join = nullptr, ev_gate = nullptr, ev_loss = nullptr;
    if (!s2) {
        cudaStreamCreateWithFlags(&s2, cudaStreamNonBlocking);
        cudaStreamCreateWithFlags(&s3, cudaStreamNonBlocking);
        cudaEventCreateWithFlags(&ev_fork, cudaEventDisableTiming);
        cudaEventCreateWithFlags(&ev_join, cudaEventDisableTiming);
        cudaEventCreateWithFlags(&ev_gate, cudaEventDisableTiming);
        cudaEventCreateWithFlags(&ev_loss, cudaEventDisableTiming);
        cudaFuncSetAttribute(k_gemm_tc2, cudaFuncAttributeMaxDynamicSharedMemorySize, GEMM2_SMEM);
        cudaFuncSetAttribute(k_gemm_mma, cudaFuncAttributeMaxDynamicSharedMemorySize, MMA_SMEM);
    }

    k_init<<<1, 32>>>();

    // fork B preprocessing immediately (independent of gate weights)
    cudaEventRecord(ev_fork, 0);
    cudaStreamWaitEvent(s2, ev_fork, 0);
    k_prep_b<<<dim3(16, 256), 256, 0, s2>>>(ew);
    k_prep_bb<<<4, 256, 0, s2>>>(eb);
    cudaEventRecord(ev_join, s2);

    // gating chain
    k_prep_w<<<32, 256>>>(wg, wn);
    k_logits<<<Bn / 4, 512>>>(x, noise);
    k_gate<<<Bn / 256, 256>>>();

    // loss on s3 (off the GEMM critical path), joined back AFTER the GEMM
    cudaEventRecord(ev_gate, 0);
    cudaStreamWaitEvent(s3, ev_gate, 0);
    k_loss<<<1, 32, 0, s3>>>(out);
    cudaEventRecord(ev_loss, s3);

    // join prep, then GEMM (occupancy 2: all 256 CTAs co-resident)
    cudaStreamWaitEvent(0, ev_join, 0);
    k_gemm_tc2<<<dim3(Hn / TC_NT, Bn / TC_MT), 576, GEMM2_SMEM>>>(x, out);

    // mma.sync fallback (early-exits if tc path is live)
    k_gemm_mma<<<dim3(Hn / BN, Bn / BM), 256, MMA_SMEM>>>(x, ew, eb, out);

    // rejoin s3 so the capture graph has no unjoined work
    cudaStreamWaitEvent(0, ev_loss, 0);
}